// round 5
// baseline (speedup 1.0000x reference)
#include <cuda_runtime.h>
#include <math.h>
#include <stdint.h>

// Problem constants
// N=16, C=128, T=128, V=25, K=3, H=8, OC=256, C/H=16, OC/H=32
// x: (16,128,128,25)  out: (16,256,128,25)

#define TV 3200          // T*V
#define CTV 409600       // C*T*V

// ---- scratch (device globals; allocation-free) ----
__device__ float d_BnA[24 * 625];
__device__ float d_bsum[256];
__device__ float d_res_pre[16 * 256 * 3200];   // [n][ch][t][w] 52.4 MB
__device__ float d_out_pre2[16 * 8 * 128 * 800]; // [n][h][t][ow] 52.4 MB
__device__ float d_G2[8 * 896 * 512];          // fused main weights, 14.7 MB
__device__ float d_ss[1024];
__device__ float d_rpart[800 * 256];           // res-path BN partials
__device__ float d_mpart[8 * 7 * 16 * 128 * 2]; // main-path BN partials

__device__ __forceinline__ uint32_t f2tf32(float f) {
    uint32_t r;
    asm("cvt.rna.tf32.f32 %0, %1;" : "=r"(r) : "f"(f));
    return r;
}
__device__ __forceinline__ void mma_tf32(float c[4], const uint32_t a[4],
                                         const uint32_t b[2]) {
    asm volatile(
        "mma.sync.aligned.m16n8k8.row.col.f32.tf32.tf32.f32 "
        "{%0,%1,%2,%3},{%4,%5,%6,%7},{%8,%9},{%0,%1,%2,%3};"
        : "+f"(c[0]), "+f"(c[1]), "+f"(c[2]), "+f"(c[3])
        : "r"(a[0]), "r"(a[1]), "r"(a[2]), "r"(a[3]), "r"(b[0]), "r"(b[1]));
}

// ---------------------------------------------------------------------------
// Kernel 1: build BnA and summed bias.
// ---------------------------------------------------------------------------
__global__ void prep_kernel(const int* __restrict__ hop,
                            const float* __restrict__ emb,
                            const float* __restrict__ A,
                            const float* __restrict__ b_block) {
    int g = blockIdx.x;
    int w = threadIdx.x;
    if (g < 24) {
        if (w < 25) {
            const float* eg = emb + g * 12;
            const float* Ag = A + g * 625;
            float sb = 0.f, sa = 0.f;
            for (int v = 0; v < 25; ++v) {
                float bv = eg[hop[v * 25 + w]];
                float av = Ag[v * 25 + w];
                sb += bv * bv;
                sa += av * av;
            }
            float rb = 1.f / (sqrtf(sb) + 1e-4f);
            float ra = 1.f / (sqrtf(sa) + 1e-4f);
            for (int v = 0; v < 25; ++v) {
                float bv = eg[hop[v * 25 + w]];
                float av = Ag[v * 25 + w];
                d_BnA[g * 625 + v * 25 + w] = bv * rb + av * ra;
            }
        }
    } else {
        for (int oc = w; oc < 256; oc += 32)
            d_bsum[oc] = b_block[oc] + b_block[256 + oc] + b_block[512 + oc];
    }
}

// ---------------------------------------------------------------------------
// Kernel 1b: build fused weights G2[h][o*25+w][c*32+v] = sum_k wg*BnA.
// Pad v 25->32 (zeros), pad rows 800->896 (zeros).
// ---------------------------------------------------------------------------
__global__ __launch_bounds__(256) void gbuild_kernel(
    const float* __restrict__ w_block) {
    int o = blockIdx.x;   // 0..32 (32 = pad block)
    int h = blockIdx.y;
    int tid = threadIdx.x;
    if (o == 32) {
        float* dst = d_G2 + (h * 896 + 800) * 512;
        for (int idx = tid; idx < 96 * 512; idx += 256) dst[idx] = 0.f;
        return;
    }
    __shared__ float bna[3 * 625];
    __shared__ float wg3[48];
    for (int idx = tid; idx < 1875; idx += 256) {
        int k = idx / 625;
        bna[idx] = d_BnA[(k * 8 + h) * 625 + (idx - k * 625)];
    }
    if (tid < 48) {
        int k = tid / 16, c = tid & 15;
        wg3[tid] = w_block[(k * 8 + h) * 512 + o * 16 + c];
    }
    __syncthreads();
    float* dst = d_G2 + (h * 896 + o * 25) * 512;
    for (int idx = tid; idx < 12800; idx += 256) {
        int w = idx >> 9, cvp = idx & 511;
        int c = cvp >> 5, v = cvp & 31;
        float val = 0.f;
        if (v < 25) {
            int vw = v * 25 + w;
            val = wg3[c] * bna[vw] + wg3[16 + c] * bna[625 + vw] +
                  wg3[32 + c] * bna[1250 + vw];
        }
        dst[w * 512 + cvp] = val;
    }
}

// ---------------------------------------------------------------------------
// Kernel 2: res GEMM on mma.sync tf32 (m16n8k8). (validated round 4)
// ---------------------------------------------------------------------------
#define RES_SMEM_BYTES ((16896 + 16896 + 512) * 4)

__global__ __launch_bounds__(256) void res_gemm_tc(
    const float* __restrict__ x,
    const float* __restrict__ res_w,
    const float* __restrict__ res_b) {
    extern __shared__ __align__(16) float smem[];
    float* As = smem;
    float* Bs = smem + 16896;
    float* part = smem + 33792;

    const int tid = threadIdx.x;
    const int wid = tid >> 5, lane = tid & 31;
    const int gid = lane >> 2, tg = lane & 3;
    const int warp_m = wid >> 1;
    const int warp_n = wid & 1;
    const int tv0 = blockIdx.x * 128;
    const int o0 = blockIdx.y * 128;
    const int n = blockIdx.z;

    {
        const float4* wsrc = (const float4*)(res_w + o0 * 128);
#pragma unroll
        for (int it = 0; it < 16; ++it) {
            int idx = tid + it * 256;
            int o = idx >> 5, c4 = idx & 31;
            float4 v = wsrc[o * 32 + c4];
            uint4 t;
            t.x = f2tf32(v.x); t.y = f2tf32(v.y);
            t.z = f2tf32(v.z); t.w = f2tf32(v.w);
            *(uint4*)(As + o * 132 + c4 * 4) = t;
        }
    }
    {
        const float* xn = x + n * CTV + tv0;
#pragma unroll
        for (int it = 0; it < 16; ++it) {
            int idx = tid + it * 256;
            int c = idx >> 5, j4 = idx & 31;
            float4 v = *(const float4*)(xn + c * TV + j4 * 4);
            uint32_t* b = (uint32_t*)Bs;
            b[(j4 * 4 + 0) * 132 + c] = f2tf32(v.x);
            b[(j4 * 4 + 1) * 132 + c] = f2tf32(v.y);
            b[(j4 * 4 + 2) * 132 + c] = f2tf32(v.z);
            b[(j4 * 4 + 3) * 132 + c] = f2tf32(v.w);
        }
    }
    __syncthreads();

    float c[2][8][4];
#pragma unroll
    for (int mt = 0; mt < 2; ++mt)
#pragma unroll
        for (int nt = 0; nt < 8; ++nt)
#pragma unroll
            for (int q = 0; q < 4; ++q) c[mt][nt][q] = 0.f;

    const uint32_t* Au = (const uint32_t*)As;
    const uint32_t* Bu = (const uint32_t*)Bs;
    const int arow = (warp_m * 32 + gid) * 132 + tg;
    const int brow = (warp_n * 64 + gid) * 132 + tg;

#pragma unroll
    for (int step = 0; step < 16; ++step) {
        const int k0 = step * 8;
        uint32_t a[2][4], b[8][2];
#pragma unroll
        for (int mt = 0; mt < 2; ++mt) {
            int base = arow + mt * 16 * 132 + k0;
            a[mt][0] = Au[base];
            a[mt][1] = Au[base + 8 * 132];
            a[mt][2] = Au[base + 4];
            a[mt][3] = Au[base + 8 * 132 + 4];
        }
#pragma unroll
        for (int nt = 0; nt < 8; ++nt) {
            int base = brow + nt * 8 * 132 + k0;
            b[nt][0] = Bu[base];
            b[nt][1] = Bu[base + 4];
        }
#pragma unroll
        for (int mt = 0; mt < 2; ++mt)
#pragma unroll
            for (int nt = 0; nt < 8; ++nt)
                mma_tf32(c[mt][nt], a[mt], b[nt]);
    }

    const int colbase = tv0 + warp_n * 64 + 2 * tg;
#pragma unroll
    for (int mt = 0; mt < 2; ++mt) {
        int row0 = o0 + warp_m * 32 + mt * 16 + gid;
        float bias0 = res_b[row0];
        float bias1 = res_b[row0 + 8];
        float s0 = 0.f, q0 = 0.f, s1 = 0.f, q1 = 0.f;
        float* dst0 = d_res_pre + (n * 256 + row0) * TV;
        float* dst1 = dst0 + 8 * TV;
#pragma unroll
        for (int nt = 0; nt < 8; ++nt) {
            float v0 = c[mt][nt][0] + bias0;
            float v1 = c[mt][nt][1] + bias0;
            float v2 = c[mt][nt][2] + bias1;
            float v3 = c[mt][nt][3] + bias1;
            s0 += v0 + v1;  q0 += v0 * v0 + v1 * v1;
            s1 += v2 + v3;  q1 += v2 * v2 + v3 * v3;
            int col = colbase + nt * 8;
            *(float2*)(dst0 + col) = make_float2(v0, v1);
            *(float2*)(dst1 + col) = make_float2(v2, v3);
        }
#pragma unroll
        for (int off = 1; off <= 2; off <<= 1) {
            s0 += __shfl_xor_sync(0xFFFFFFFFu, s0, off);
            q0 += __shfl_xor_sync(0xFFFFFFFFu, q0, off);
            s1 += __shfl_xor_sync(0xFFFFFFFFu, s1, off);
            q1 += __shfl_xor_sync(0xFFFFFFFFu, q1, off);
        }
        if (tg == 0) {
            int r = warp_m * 32 + mt * 16 + gid;
            part[(warp_n * 128 + r) * 2] = s0;
            part[(warp_n * 128 + r) * 2 + 1] = q0;
            part[(warp_n * 128 + r + 8) * 2] = s1;
            part[(warp_n * 128 + r + 8) * 2 + 1] = q1;
        }
    }
    __syncthreads();
    if (tid < 128) {
        float s = part[tid * 2] + part[(128 + tid) * 2];
        float q = part[tid * 2 + 1] + part[(128 + tid) * 2 + 1];
        int blk = (n * 2 + blockIdx.y) * 25 + blockIdx.x;
        d_rpart[blk * 256 + tid * 2] = s;
        d_rpart[blk * 256 + tid * 2 + 1] = q;
    }
}

// ---------------------------------------------------------------------------
// Kernel 3: main path fused GEMM on mma.sync tf32.
// Per CTA: D[128 ow rows @ m0][128 t cols] = G2[h] (x) x[n,h], K = 512 (padded
// c*32+v). K-chunks of 64 (= 2 c's). Output -> d_out_pre2[n][h][t][ow],
// coalesced stores (lanes = consecutive rows). BN partials in epilogue.
// ---------------------------------------------------------------------------
#define MAIN_SMEM_BYTES ((8704 + 8704 + 512) * 4)

__global__ __launch_bounds__(256) void main_gemm_tc(
    const float* __restrict__ x) {
    extern __shared__ __align__(16) float smem[];
    float* As = smem;            // [128 rows][68]
    float* Bs = smem + 8704;     // [128 t][68]
    float* part = smem + 17408;  // [2][128][2]

    const int tid = threadIdx.x;
    const int wid = tid >> 5, lane = tid & 31;
    const int gid = lane >> 2, tg = lane & 3;
    const int warp_m = wid >> 1;
    const int warp_n = wid & 1;
    const int n = blockIdx.x;
    const int mb = blockIdx.y;
    const int m0 = mb * 128;
    const int h = blockIdx.z;

    float c[2][8][4];
#pragma unroll
    for (int mt = 0; mt < 2; ++mt)
#pragma unroll
        for (int nt = 0; nt < 8; ++nt)
#pragma unroll
            for (int q = 0; q < 4; ++q) c[mt][nt][q] = 0.f;

    const uint32_t* Au = (const uint32_t*)As;
    const uint32_t* Bu = (const uint32_t*)Bs;
    const int arow = (warp_m * 32 + gid) * 68 + tg;
    const int brow = (warp_n * 64 + gid) * 68 + tg;
    const float* gbase = d_G2 + (h * 896 + m0) * 512;
    const float* xbase = x + n * CTV + h * 16 * TV;

    for (int q = 0; q < 8; ++q) {
        const int kc0 = q * 64;
        __syncthreads();
        // Stage A: G2 rows, float4 coalesced
#pragma unroll
        for (int it = 0; it < 8; ++it) {
            int idx = tid + it * 256;           // 0..2047
            int row = idx >> 4, f4 = idx & 15;
            float4 v = *(const float4*)(gbase + row * 512 + kc0 + f4 * 4);
            uint4 t;
            t.x = f2tf32(v.x); t.y = f2tf32(v.y);
            t.z = f2tf32(v.z); t.w = f2tf32(v.w);
            *(uint4*)(As + row * 68 + f4 * 4) = t;
        }
        // Stage B: x gather (2 c's x 128 t x 32 v, zeros at v>=25)
        const float* xc = xbase + q * 2 * TV;
#pragma unroll
        for (int it = 0; it < 32; ++it) {
            int idx = tid + it * 256;           // 0..8191
            int cp = idx >> 12, r = idx & 4095;
            int t = r >> 5, v = r & 31;
            float val = (v < 25) ? xc[cp * TV + t * 25 + v] : 0.f;
            *(uint32_t*)(Bs + t * 68 + cp * 32 + v) = f2tf32(val);
        }
        __syncthreads();

#pragma unroll
        for (int step = 0; step < 8; ++step) {
            const int k0 = step * 8;
            uint32_t a[2][4], b[8][2];
#pragma unroll
            for (int mt = 0; mt < 2; ++mt) {
                int base = arow + mt * 16 * 68 + k0;
                a[mt][0] = Au[base];
                a[mt][1] = Au[base + 8 * 68];
                a[mt][2] = Au[base + 4];
                a[mt][3] = Au[base + 8 * 68 + 4];
            }
#pragma unroll
            for (int nt = 0; nt < 8; ++nt) {
                int base = brow + nt * 8 * 68 + k0;
                b[nt][0] = Bu[base];
                b[nt][1] = Bu[base + 4];
            }
#pragma unroll
            for (int mt = 0; mt < 2; ++mt)
#pragma unroll
                for (int nt = 0; nt < 8; ++nt)
                    mma_tf32(c[mt][nt], a[mt], b[nt]);
        }
    }

    // Epilogue: bias, coalesced store to [n][h][t][ow], BN partials.
    float* obase = d_out_pre2 + (n * 8 + h) * 128 * 800;
#pragma unroll
    for (int mt = 0; mt < 2; ++mt) {
        int r0 = m0 + warp_m * 32 + mt * 16 + gid;  // rows r0, r0+8
        int o0 = r0 / 25, o1 = (r0 + 8) / 25;
        float bias0 = (r0 < 800) ? d_bsum[h * 32 + o0] : 0.f;
        float bias1 = (r0 + 8 < 800) ? d_bsum[h * 32 + o1] : 0.f;
        float s0 = 0.f, q0 = 0.f, s1 = 0.f, q1 = 0.f;
        int colbase = warp_n * 64 + 2 * tg;
#pragma unroll
        for (int nt = 0; nt < 8; ++nt) {
            float v0 = c[mt][nt][0] + bias0;
            float v1 = c[mt][nt][1] + bias0;
            float v2 = c[mt][nt][2] + bias1;
            float v3 = c[mt][nt][3] + bias1;
            s0 += v0 + v1;  q0 += v0 * v0 + v1 * v1;
            s1 += v2 + v3;  q1 += v2 * v2 + v3 * v3;
            int col = colbase + nt * 8;
            if (r0 < 800) {
                obase[col * 800 + r0] = v0;
                obase[(col + 1) * 800 + r0] = v1;
            }
            if (r0 + 8 < 800) {
                obase[col * 800 + r0 + 8] = v2;
                obase[(col + 1) * 800 + r0 + 8] = v3;
            }
        }
#pragma unroll
        for (int off = 1; off <= 2; off <<= 1) {
            s0 += __shfl_xor_sync(0xFFFFFFFFu, s0, off);
            q0 += __shfl_xor_sync(0xFFFFFFFFu, q0, off);
            s1 += __shfl_xor_sync(0xFFFFFFFFu, s1, off);
            q1 += __shfl_xor_sync(0xFFFFFFFFu, q1, off);
        }
        if (tg == 0) {
            int r = warp_m * 32 + mt * 16 + gid;
            part[(warp_n * 128 + r) * 2] = s0;
            part[(warp_n * 128 + r) * 2 + 1] = q0;
            part[(warp_n * 128 + r + 8) * 2] = s1;
            part[(warp_n * 128 + r + 8) * 2 + 1] = q1;
        }
    }
    __syncthreads();
    if (tid < 128) {
        float s = part[tid * 2] + part[(128 + tid) * 2];
        float q = part[tid * 2 + 1] + part[(128 + tid) * 2 + 1];
        int blk = (h * 7 + mb) * 16 + n;
        d_mpart[(blk * 128 + tid) * 2] = s;
        d_mpart[(blk * 128 + tid) * 2 + 1] = q;
    }
}

// ---------------------------------------------------------------------------
// Kernel 4a: out-path BN stats from GEMM partials. One block / channel.
// ---------------------------------------------------------------------------
__global__ __launch_bounds__(128) void stats_out_kernel(
    const float* __restrict__ bn_gamma, const float* __restrict__ bn_beta) {
    __shared__ float ssum[128];
    __shared__ float ssq[128];
    int ch = blockIdx.x;
    int h = ch >> 5, o = ch & 31;
    int tid = threadIdx.x;

    float s = 0.f, q = 0.f;
    for (int e = tid; e < 400; e += 128) {   // 25 w x 16 n
        int w = e >> 4, nn = e & 15;
        int grow = o * 25 + w;
        int mb = grow >> 7, lr = grow & 127;
        int blk = (h * 7 + mb) * 16 + nn;
        s += d_mpart[(blk * 128 + lr) * 2];
        q += d_mpart[(blk * 128 + lr) * 2 + 1];
    }
    ssum[tid] = s;
    ssq[tid] = q;
    __syncthreads();
    for (int st = 64; st > 0; st >>= 1) {
        if (tid < st) {
            ssum[tid] += ssum[tid + st];
            ssq[tid] += ssq[tid + st];
        }
        __syncthreads();
    }
    if (tid == 0) {
        const float inv = 1.f / 51200.f;
        float mean = ssum[0] * inv;
        float var = ssq[0] * inv - mean * mean;
        float sc = bn_gamma[ch] * rsqrtf(var + 1e-5f);
        d_ss[ch] = sc;
        d_ss[256 + ch] = bn_beta[ch] - mean * sc;
    }
}

// ---------------------------------------------------------------------------
// Kernel 4b: res-path BN stats from GEMM partials. One block / channel.
// ---------------------------------------------------------------------------
__global__ __launch_bounds__(128) void stats_res_kernel(
    const float* __restrict__ res_bn_gamma, const float* __restrict__ res_bn_beta) {
    __shared__ float ssum[128];
    __shared__ float ssq[128];
    int ch = blockIdx.x;
    int ob = ch >> 7, row = ch & 127;
    int tid = threadIdx.x;

    float s = 0.f, q = 0.f;
    for (int e = tid; e < 400; e += 128) {
        int nn = e / 25, tvb = e - nn * 25;
        int blk = (nn * 2 + ob) * 25 + tvb;
        s += d_rpart[blk * 256 + row * 2];
        q += d_rpart[blk * 256 + row * 2 + 1];
    }
    ssum[tid] = s;
    ssq[tid] = q;
    __syncthreads();
    for (int st = 64; st > 0; st >>= 1) {
        if (tid < st) {
            ssum[tid] += ssum[tid + st];
            ssq[tid] += ssq[tid + st];
        }
        __syncthreads();
    }
    if (tid == 0) {
        const float inv = 1.f / 51200.f;
        float mean = ssum[0] * inv;
        float var = ssq[0] * inv - mean * mean;
        float sc = res_bn_gamma[ch] * rsqrtf(var + 1e-5f);
        d_ss[512 + ch] = sc;
        d_ss[768 + ch] = res_bn_beta[ch] - mean * sc;
    }
}

// ---------------------------------------------------------------------------
// Kernel 5: out = relu(BN(out_pre2) + BN(res_pre)). One block per (n,t).
// ---------------------------------------------------------------------------
__global__ __launch_bounds__(256) void final_kernel(float* __restrict__ out) {
    int b = blockIdx.x;
    int n = b >> 7, t = b & 127;
    int tid = threadIdx.x;
    const float* p2 = d_out_pre2 + (n * 8) * 128 * 800 + t * 800;
#pragma unroll
    for (int it = 0; it < 25; ++it) {
        int idx = it * 256 + tid;          // 0..6399
        int ch = idx / 25, w = idx - ch * 25;
        int h = ch >> 5, o = ch & 31;
        float op = p2[h * 128 * 800 + o * 25 + w];
        float rp = d_res_pre[((n * 256 + ch) * 128 + t) * 25 + w];
        float so = d_ss[ch], ho = d_ss[256 + ch];
        float sr = d_ss[512 + ch], hr = d_ss[768 + ch];
        float r = fmaxf(fmaf(op, so, ho) + fmaf(rp, sr, hr), 0.f);
        out[((n * 256 + ch) * 128 + t) * 25 + w] = r;
    }
}

// ---------------------------------------------------------------------------
extern "C" void kernel_launch(void* const* d_in, const int* in_sizes, int n_in,
                              void* d_out, int out_size) {
    const float* x            = (const float*)d_in[0];
    const int*   hop          = (const int*)d_in[1];
    const float* emb          = (const float*)d_in[2];
    const float* A            = (const float*)d_in[3];
    const float* w_block      = (const float*)d_in[4];
    const float* b_block      = (const float*)d_in[5];
    const float* bn_gamma     = (const float*)d_in[6];
    const float* bn_beta      = (const float*)d_in[7];
    const float* res_w        = (const float*)d_in[8];
    const float* res_b        = (const float*)d_in[9];
    const float* res_bn_gamma = (const float*)d_in[10];
    const float* res_bn_beta  = (const float*)d_in[11];
    float* out = (float*)d_out;

    cudaFuncSetAttribute(res_gemm_tc, cudaFuncAttributeMaxDynamicSharedMemorySize,
                         RES_SMEM_BYTES);
    cudaFuncSetAttribute(main_gemm_tc, cudaFuncAttributeMaxDynamicSharedMemorySize,
                         MAIN_SMEM_BYTES);

    prep_kernel<<<25, 32>>>(hop, emb, A, b_block);
    gbuild_kernel<<<dim3(33, 8), 256>>>(w_block);
    res_gemm_tc<<<dim3(25, 2, 16), 256, RES_SMEM_BYTES>>>(x, res_w, res_b);
    main_gemm_tc<<<dim3(16, 7, 8), 256, MAIN_SMEM_BYTES>>>(x);
    stats_out_kernel<<<256, 128>>>(bn_gamma, bn_beta);
    stats_res_kernel<<<256, 128>>>(res_bn_gamma, res_bn_beta);
    final_kernel<<<2048, 256>>>(out);
}

// round 6
// speedup vs baseline: 1.2238x; 1.2238x over previous
#include <cuda_runtime.h>
#include <math.h>
#include <stdint.h>

// Problem constants
// N=16, C=128, T=128, V=25, K=3, H=8, OC=256, C/H=16, OC/H=32
// x: (16,128,128,25)  out: (16,256,128,25)

#define TV 3200          // T*V
#define CTV 409600       // C*T*V

// ---- scratch (device globals; allocation-free) ----
__device__ float d_BnA[24 * 625];
__device__ float d_bsum[256];
__device__ float d_res_pre[16 * 256 * 3200];     // [n][ch][t][w] 52.4 MB
__device__ float d_out_pre2[16 * 8 * 128 * 800]; // [n][h][t][ow] 52.4 MB
__device__ float d_G2[8 * 896 * 400];            // fused weights (tf32 bits) 11.5 MB
__device__ float d_xr[16 * 8 * 128 * 400];       // x transposed (tf32 bits) 26.2 MB
__device__ float d_ss[1024];
__device__ float d_rpart[800 * 256];             // res-path BN partials
__device__ float d_mpart[8 * 7 * 16 * 128 * 2];  // main-path BN partials

__device__ __forceinline__ uint32_t f2tf32(float f) {
    uint32_t r;
    asm("cvt.rna.tf32.f32 %0, %1;" : "=r"(r) : "f"(f));
    return r;
}
__device__ __forceinline__ void mma_tf32(float c[4], const uint32_t a[4],
                                         const uint32_t b[2]) {
    asm volatile(
        "mma.sync.aligned.m16n8k8.row.col.f32.tf32.tf32.f32 "
        "{%0,%1,%2,%3},{%4,%5,%6,%7},{%8,%9},{%0,%1,%2,%3};"
        : "+f"(c[0]), "+f"(c[1]), "+f"(c[2]), "+f"(c[3])
        : "r"(a[0]), "r"(a[1]), "r"(a[2]), "r"(a[3]), "r"(b[0]), "r"(b[1]));
}

// ---------------------------------------------------------------------------
// Kernel 1: build BnA and summed bias.
// ---------------------------------------------------------------------------
__global__ void prep_kernel(const int* __restrict__ hop,
                            const float* __restrict__ emb,
                            const float* __restrict__ A,
                            const float* __restrict__ b_block) {
    int g = blockIdx.x;
    int w = threadIdx.x;
    if (g < 24) {
        if (w < 25) {
            const float* eg = emb + g * 12;
            const float* Ag = A + g * 625;
            float sb = 0.f, sa = 0.f;
            for (int v = 0; v < 25; ++v) {
                float bv = eg[hop[v * 25 + w]];
                float av = Ag[v * 25 + w];
                sb += bv * bv;
                sa += av * av;
            }
            float rb = 1.f / (sqrtf(sb) + 1e-4f);
            float ra = 1.f / (sqrtf(sa) + 1e-4f);
            for (int v = 0; v < 25; ++v) {
                float bv = eg[hop[v * 25 + w]];
                float av = Ag[v * 25 + w];
                d_BnA[g * 625 + v * 25 + w] = bv * rb + av * ra;
            }
        }
    } else {
        for (int oc = w; oc < 256; oc += 32)
            d_bsum[oc] = b_block[oc] + b_block[256 + oc] + b_block[512 + oc];
    }
}

// ---------------------------------------------------------------------------
// Kernel 1b: G2[h][o*25+w][c*25+v] = sum_k wg*BnA, stored as tf32 BITS.
// Rows padded 800->896 with zeros. K = 400 (no v padding).
// ---------------------------------------------------------------------------
__global__ __launch_bounds__(256) void gbuild_kernel(
    const float* __restrict__ w_block) {
    int o = blockIdx.x;   // 0..32 (32 = row-pad block)
    int h = blockIdx.y;
    int tid = threadIdx.x;
    if (o == 32) {
        float* dst = d_G2 + (h * 896 + 800) * 400;
        for (int idx = tid; idx < 96 * 400; idx += 256) dst[idx] = 0.f;
        return;
    }
    __shared__ float bna[3 * 625];
    __shared__ float wg3[48];
    for (int idx = tid; idx < 1875; idx += 256) {
        int k = idx / 625;
        bna[idx] = d_BnA[(k * 8 + h) * 625 + (idx - k * 625)];
    }
    if (tid < 48) {
        int k = tid / 16, c = tid & 15;
        wg3[tid] = w_block[(k * 8 + h) * 512 + o * 16 + c];
    }
    __syncthreads();
    float* dst = d_G2 + (h * 896 + o * 25) * 400;
    for (int idx = tid; idx < 10000; idx += 256) {   // 25 w x 400 cv
        int w = idx / 400, cv = idx - w * 400;
        int c = cv / 25, v = cv - c * 25;
        int vw = v * 25 + w;
        float val = wg3[c] * bna[vw] + wg3[16 + c] * bna[625 + vw] +
                    wg3[32 + c] * bna[1250 + vw];
        dst[w * 400 + cv] = __uint_as_float(f2tf32(val));
    }
}

// ---------------------------------------------------------------------------
// Kernel 1c: transpose x -> d_xr[n][h][t][c*25+v] as tf32 BITS.
// ---------------------------------------------------------------------------
__global__ __launch_bounds__(256) void xr_kernel(const float* __restrict__ x) {
    int n = blockIdx.x, h = blockIdx.y;
    int tid = threadIdx.x;
    const float* xb = x + n * CTV + h * 16 * TV;
    float* dst = d_xr + (n * 8 + h) * 128 * 400;
#pragma unroll
    for (int it = 0; it < 200; ++it) {
        int idx = it * 256 + tid;            // 0..51199
        int t = idx / 400, j = idx - t * 400;
        int c = j / 25, v = j - c * 25;
        dst[idx] = __uint_as_float(f2tf32(xb[c * TV + t * 25 + v]));
    }
}

// ---------------------------------------------------------------------------
// Kernel 2: res GEMM on mma.sync tf32 (validated round 4, unchanged).
// ---------------------------------------------------------------------------
#define RES_SMEM_BYTES ((16896 + 16896 + 512) * 4)

__global__ __launch_bounds__(256) void res_gemm_tc(
    const float* __restrict__ x,
    const float* __restrict__ res_w,
    const float* __restrict__ res_b) {
    extern __shared__ __align__(16) float smem[];
    float* As = smem;
    float* Bs = smem + 16896;
    float* part = smem + 33792;

    const int tid = threadIdx.x;
    const int wid = tid >> 5, lane = tid & 31;
    const int gid = lane >> 2, tg = lane & 3;
    const int warp_m = wid >> 1;
    const int warp_n = wid & 1;
    const int tv0 = blockIdx.x * 128;
    const int o0 = blockIdx.y * 128;
    const int n = blockIdx.z;

    {
        const float4* wsrc = (const float4*)(res_w + o0 * 128);
#pragma unroll
        for (int it = 0; it < 16; ++it) {
            int idx = tid + it * 256;
            int o = idx >> 5, c4 = idx & 31;
            float4 v = wsrc[o * 32 + c4];
            uint4 t;
            t.x = f2tf32(v.x); t.y = f2tf32(v.y);
            t.z = f2tf32(v.z); t.w = f2tf32(v.w);
            *(uint4*)(As + o * 132 + c4 * 4) = t;
        }
    }
    {
        const float* xn = x + n * CTV + tv0;
#pragma unroll
        for (int it = 0; it < 16; ++it) {
            int idx = tid + it * 256;
            int c = idx >> 5, j4 = idx & 31;
            float4 v = *(const float4*)(xn + c * TV + j4 * 4);
            uint32_t* b = (uint32_t*)Bs;
            b[(j4 * 4 + 0) * 132 + c] = f2tf32(v.x);
            b[(j4 * 4 + 1) * 132 + c] = f2tf32(v.y);
            b[(j4 * 4 + 2) * 132 + c] = f2tf32(v.z);
            b[(j4 * 4 + 3) * 132 + c] = f2tf32(v.w);
        }
    }
    __syncthreads();

    float c[2][8][4];
#pragma unroll
    for (int mt = 0; mt < 2; ++mt)
#pragma unroll
        for (int nt = 0; nt < 8; ++nt)
#pragma unroll
            for (int q = 0; q < 4; ++q) c[mt][nt][q] = 0.f;

    const uint32_t* Au = (const uint32_t*)As;
    const uint32_t* Bu = (const uint32_t*)Bs;
    const int arow = (warp_m * 32 + gid) * 132 + tg;
    const int brow = (warp_n * 64 + gid) * 132 + tg;

#pragma unroll
    for (int step = 0; step < 16; ++step) {
        const int k0 = step * 8;
        uint32_t a[2][4], b[8][2];
#pragma unroll
        for (int mt = 0; mt < 2; ++mt) {
            int base = arow + mt * 16 * 132 + k0;
            a[mt][0] = Au[base];
            a[mt][1] = Au[base + 8 * 132];
            a[mt][2] = Au[base + 4];
            a[mt][3] = Au[base + 8 * 132 + 4];
        }
#pragma unroll
        for (int nt = 0; nt < 8; ++nt) {
            int base = brow + nt * 8 * 132 + k0;
            b[nt][0] = Bu[base];
            b[nt][1] = Bu[base + 4];
        }
#pragma unroll
        for (int mt = 0; mt < 2; ++mt)
#pragma unroll
            for (int nt = 0; nt < 8; ++nt)
                mma_tf32(c[mt][nt], a[mt], b[nt]);
    }

    const int colbase = tv0 + warp_n * 64 + 2 * tg;
#pragma unroll
    for (int mt = 0; mt < 2; ++mt) {
        int row0 = o0 + warp_m * 32 + mt * 16 + gid;
        float bias0 = res_b[row0];
        float bias1 = res_b[row0 + 8];
        float s0 = 0.f, q0 = 0.f, s1 = 0.f, q1 = 0.f;
        float* dst0 = d_res_pre + (n * 256 + row0) * TV;
        float* dst1 = dst0 + 8 * TV;
#pragma unroll
        for (int nt = 0; nt < 8; ++nt) {
            float v0 = c[mt][nt][0] + bias0;
            float v1 = c[mt][nt][1] + bias0;
            float v2 = c[mt][nt][2] + bias1;
            float v3 = c[mt][nt][3] + bias1;
            s0 += v0 + v1;  q0 += v0 * v0 + v1 * v1;
            s1 += v2 + v3;  q1 += v2 * v2 + v3 * v3;
            int col = colbase + nt * 8;
            *(float2*)(dst0 + col) = make_float2(v0, v1);
            *(float2*)(dst1 + col) = make_float2(v2, v3);
        }
#pragma unroll
        for (int off = 1; off <= 2; off <<= 1) {
            s0 += __shfl_xor_sync(0xFFFFFFFFu, s0, off);
            q0 += __shfl_xor_sync(0xFFFFFFFFu, q0, off);
            s1 += __shfl_xor_sync(0xFFFFFFFFu, s1, off);
            q1 += __shfl_xor_sync(0xFFFFFFFFu, q1, off);
        }
        if (tg == 0) {
            int r = warp_m * 32 + mt * 16 + gid;
            part[(warp_n * 128 + r) * 2] = s0;
            part[(warp_n * 128 + r) * 2 + 1] = q0;
            part[(warp_n * 128 + r + 8) * 2] = s1;
            part[(warp_n * 128 + r + 8) * 2 + 1] = q1;
        }
    }
    __syncthreads();
    if (tid < 128) {
        float s = part[tid * 2] + part[(128 + tid) * 2];
        float q = part[tid * 2 + 1] + part[(128 + tid) * 2 + 1];
        int blk = (n * 2 + blockIdx.y) * 25 + blockIdx.x;
        d_rpart[blk * 256 + tid * 2] = s;
        d_rpart[blk * 256 + tid * 2 + 1] = q;
    }
}

// ---------------------------------------------------------------------------
// Kernel 3: main fused GEMM, v2. K=400 (5 chunks of 80), operands are
// pre-converted tf32 bits -> staging is pure float4 copies. smem stride 84
// (conflict-free). __launch_bounds__(256,2) for 2 CTAs/SM.
// ---------------------------------------------------------------------------
#define MAIN_SMEM_BYTES ((10752 + 10752 + 512) * 4)

__global__ __launch_bounds__(256, 2) void main_gemm_tc() {
    extern __shared__ __align__(16) float smem[];
    float* As = smem;            // [128 rows][84]
    float* Bs = smem + 10752;    // [128 t][84]
    float* part = smem + 21504;  // [2][128][2]

    const int tid = threadIdx.x;
    const int wid = tid >> 5, lane = tid & 31;
    const int gid = lane >> 2, tg = lane & 3;
    const int warp_m = wid >> 1;
    const int warp_n = wid & 1;
    const int n = blockIdx.x;
    const int mb = blockIdx.y;
    const int m0 = mb * 128;
    const int h = blockIdx.z;

    float c[2][8][4];
#pragma unroll
    for (int mt = 0; mt < 2; ++mt)
#pragma unroll
        for (int nt = 0; nt < 8; ++nt)
#pragma unroll
            for (int q = 0; q < 4; ++q) c[mt][nt][q] = 0.f;

    const uint32_t* Au = (const uint32_t*)As;
    const uint32_t* Bu = (const uint32_t*)Bs;
    const int arow = (warp_m * 32 + gid) * 84 + tg;
    const int brow = (warp_n * 64 + gid) * 84 + tg;
    const float* gbase = d_G2 + (h * 896 + m0) * 400;
    const float* xbase = d_xr + (n * 8 + h) * 128 * 400;

    for (int q = 0; q < 5; ++q) {
        const int kc0 = q * 80;
        __syncthreads();
#pragma unroll
        for (int it = 0; it < 10; ++it) {
            int idx = tid + it * 256;            // 0..2559
            int row = idx / 20, f = idx - row * 20;
            *(float4*)(As + row * 84 + f * 4) =
                *(const float4*)(gbase + row * 400 + kc0 + f * 4);
        }
#pragma unroll
        for (int it = 0; it < 10; ++it) {
            int idx = tid + it * 256;
            int row = idx / 20, f = idx - row * 20;
            *(float4*)(Bs + row * 84 + f * 4) =
                *(const float4*)(xbase + row * 400 + kc0 + f * 4);
        }
        __syncthreads();

#pragma unroll
        for (int step = 0; step < 10; ++step) {
            const int k0 = step * 8;
            uint32_t a[2][4], b[8][2];
#pragma unroll
            for (int mt = 0; mt < 2; ++mt) {
                int base = arow + mt * 16 * 84 + k0;
                a[mt][0] = Au[base];
                a[mt][1] = Au[base + 8 * 84];
                a[mt][2] = Au[base + 4];
                a[mt][3] = Au[base + 8 * 84 + 4];
            }
#pragma unroll
            for (int nt = 0; nt < 8; ++nt) {
                int base = brow + nt * 8 * 84 + k0;
                b[nt][0] = Bu[base];
                b[nt][1] = Bu[base + 4];
            }
#pragma unroll
            for (int mt = 0; mt < 2; ++mt)
#pragma unroll
                for (int nt = 0; nt < 8; ++nt)
                    mma_tf32(c[mt][nt], a[mt], b[nt]);
        }
    }

    // Epilogue: bias, coalesced store to [n][h][t][ow], BN partials.
    float* obase = d_out_pre2 + (n * 8 + h) * 128 * 800;
#pragma unroll
    for (int mt = 0; mt < 2; ++mt) {
        int r0 = m0 + warp_m * 32 + mt * 16 + gid;
        int o0 = r0 / 25, o1 = (r0 + 8) / 25;
        float bias0 = (r0 < 800) ? d_bsum[h * 32 + o0] : 0.f;
        float bias1 = (r0 + 8 < 800) ? d_bsum[h * 32 + o1] : 0.f;
        float s0 = 0.f, q0 = 0.f, s1 = 0.f, q1 = 0.f;
        int colbase = warp_n * 64 + 2 * tg;
#pragma unroll
        for (int nt = 0; nt < 8; ++nt) {
            float v0 = c[mt][nt][0] + bias0;
            float v1 = c[mt][nt][1] + bias0;
            float v2 = c[mt][nt][2] + bias1;
            float v3 = c[mt][nt][3] + bias1;
            s0 += v0 + v1;  q0 += v0 * v0 + v1 * v1;
            s1 += v2 + v3;  q1 += v2 * v2 + v3 * v3;
            int col = colbase + nt * 8;
            if (r0 < 800) {
                obase[col * 800 + r0] = v0;
                obase[(col + 1) * 800 + r0] = v1;
            }
            if (r0 + 8 < 800) {
                obase[col * 800 + r0 + 8] = v2;
                obase[(col + 1) * 800 + r0 + 8] = v3;
            }
        }
#pragma unroll
        for (int off = 1; off <= 2; off <<= 1) {
            s0 += __shfl_xor_sync(0xFFFFFFFFu, s0, off);
            q0 += __shfl_xor_sync(0xFFFFFFFFu, q0, off);
            s1 += __shfl_xor_sync(0xFFFFFFFFu, s1, off);
            q1 += __shfl_xor_sync(0xFFFFFFFFu, q1, off);
        }
        if (tg == 0) {
            int r = warp_m * 32 + mt * 16 + gid;
            part[(warp_n * 128 + r) * 2] = s0;
            part[(warp_n * 128 + r) * 2 + 1] = q0;
            part[(warp_n * 128 + r + 8) * 2] = s1;
            part[(warp_n * 128 + r + 8) * 2 + 1] = q1;
        }
    }
    __syncthreads();
    if (tid < 128) {
        float s = part[tid * 2] + part[(128 + tid) * 2];
        float q = part[tid * 2 + 1] + part[(128 + tid) * 2 + 1];
        int blk = (h * 7 + mb) * 16 + n;
        d_mpart[(blk * 128 + tid) * 2] = s;
        d_mpart[(blk * 128 + tid) * 2 + 1] = q;
    }
}

// ---------------------------------------------------------------------------
// Kernel 4a: out-path BN stats from GEMM partials.
// ---------------------------------------------------------------------------
__global__ __launch_bounds__(128) void stats_out_kernel(
    const float* __restrict__ bn_gamma, const float* __restrict__ bn_beta) {
    __shared__ float ssum[128];
    __shared__ float ssq[128];
    int ch = blockIdx.x;
    int h = ch >> 5, o = ch & 31;
    int tid = threadIdx.x;

    float s = 0.f, q = 0.f;
    for (int e = tid; e < 400; e += 128) {
        int w = e >> 4, nn = e & 15;
        int grow = o * 25 + w;
        int mb = grow >> 7, lr = grow & 127;
        int blk = (h * 7 + mb) * 16 + nn;
        s += d_mpart[(blk * 128 + lr) * 2];
        q += d_mpart[(blk * 128 + lr) * 2 + 1];
    }
    ssum[tid] = s;
    ssq[tid] = q;
    __syncthreads();
    for (int st = 64; st > 0; st >>= 1) {
        if (tid < st) {
            ssum[tid] += ssum[tid + st];
            ssq[tid] += ssq[tid + st];
        }
        __syncthreads();
    }
    if (tid == 0) {
        const float inv = 1.f / 51200.f;
        float mean = ssum[0] * inv;
        float var = ssq[0] * inv - mean * mean;
        float sc = bn_gamma[ch] * rsqrtf(var + 1e-5f);
        d_ss[ch] = sc;
        d_ss[256 + ch] = bn_beta[ch] - mean * sc;
    }
}

// ---------------------------------------------------------------------------
// Kernel 4b: res-path BN stats from GEMM partials.
// ---------------------------------------------------------------------------
__global__ __launch_bounds__(128) void stats_res_kernel(
    const float* __restrict__ res_bn_gamma, const float* __restrict__ res_bn_beta) {
    __shared__ float ssum[128];
    __shared__ float ssq[128];
    int ch = blockIdx.x;
    int ob = ch >> 7, row = ch & 127;
    int tid = threadIdx.x;

    float s = 0.f, q = 0.f;
    for (int e = tid; e < 400; e += 128) {
        int nn = e / 25, tvb = e - nn * 25;
        int blk = (nn * 2 + ob) * 25 + tvb;
        s += d_rpart[blk * 256 + row * 2];
        q += d_rpart[blk * 256 + row * 2 + 1];
    }
    ssum[tid] = s;
    ssq[tid] = q;
    __syncthreads();
    for (int st = 64; st > 0; st >>= 1) {
        if (tid < st) {
            ssum[tid] += ssum[tid + st];
            ssq[tid] += ssq[tid + st];
        }
        __syncthreads();
    }
    if (tid == 0) {
        const float inv = 1.f / 51200.f;
        float mean = ssum[0] * inv;
        float var = ssq[0] * inv - mean * mean;
        float sc = res_bn_gamma[ch] * rsqrtf(var + 1e-5f);
        d_ss[512 + ch] = sc;
        d_ss[768 + ch] = res_bn_beta[ch] - mean * sc;
    }
}

// ---------------------------------------------------------------------------
// Kernel 5: out = relu(BN(out_pre2) + BN(res_pre)). One block per (n,t).
// ---------------------------------------------------------------------------
__global__ __launch_bounds__(256) void final_kernel(float* __restrict__ out) {
    int b = blockIdx.x;
    int n = b >> 7, t = b & 127;
    int tid = threadIdx.x;
    const float* p2 = d_out_pre2 + (n * 8) * 128 * 800 + t * 800;
#pragma unroll
    for (int it = 0; it < 25; ++it) {
        int idx = it * 256 + tid;          // 0..6399
        int ch = idx / 25, w = idx - ch * 25;
        int h = ch >> 5, o = ch & 31;
        float op = p2[h * 128 * 800 + o * 25 + w];
        float rp = d_res_pre[((n * 256 + ch) * 128 + t) * 25 + w];
        float so = d_ss[ch], ho = d_ss[256 + ch];
        float sr = d_ss[512 + ch], hr = d_ss[768 + ch];
        float r = fmaxf(fmaf(op, so, ho) + fmaf(rp, sr, hr), 0.f);
        out[((n * 256 + ch) * 128 + t) * 25 + w] = r;
    }
}

// ---------------------------------------------------------------------------
extern "C" void kernel_launch(void* const* d_in, const int* in_sizes, int n_in,
                              void* d_out, int out_size) {
    const float* x            = (const float*)d_in[0];
    const int*   hop          = (const int*)d_in[1];
    const float* emb          = (const float*)d_in[2];
    const float* A            = (const float*)d_in[3];
    const float* w_block      = (const float*)d_in[4];
    const float* b_block      = (const float*)d_in[5];
    const float* bn_gamma     = (const float*)d_in[6];
    const float* bn_beta      = (const float*)d_in[7];
    const float* res_w        = (const float*)d_in[8];
    const float* res_b        = (const float*)d_in[9];
    const float* res_bn_gamma = (const float*)d_in[10];
    const float* res_bn_beta  = (const float*)d_in[11];
    float* out = (float*)d_out;

    cudaFuncSetAttribute(res_gemm_tc, cudaFuncAttributeMaxDynamicSharedMemorySize,
                         RES_SMEM_BYTES);
    cudaFuncSetAttribute(main_gemm_tc, cudaFuncAttributeMaxDynamicSharedMemorySize,
                         MAIN_SMEM_BYTES);

    prep_kernel<<<25, 32>>>(hop, emb, A, b_block);
    gbuild_kernel<<<dim3(33, 8), 256>>>(w_block);
    xr_kernel<<<dim3(16, 8), 256>>>(x);
    res_gemm_tc<<<dim3(25, 2, 16), 256, RES_SMEM_BYTES>>>(x, res_w, res_b);
    main_gemm_tc<<<dim3(16, 7, 8), 256, MAIN_SMEM_BYTES>>>();
    stats_out_kernel<<<256, 128>>>(bn_gamma, bn_beta);
    stats_res_kernel<<<256, 128>>>(res_bn_gamma, res_bn_beta);
    final_kernel<<<2048, 256>>>(out);
}

// round 7
// speedup vs baseline: 1.2512x; 1.0224x over previous
#include <cuda_runtime.h>
#include <math.h>
#include <stdint.h>

// Problem constants
// N=16, C=128, T=128, V=25, K=3, H=8, OC=256, C/H=16, OC/H=32
// x: (16,128,128,25)  out: (16,256,128,25)

#define TV 3200          // T*V
#define CTV 409600       // C*T*V

// ---- scratch (device globals; allocation-free) ----
__device__ float d_BnA[24 * 625];
__device__ float d_bsum[256];
__device__ float d_res_pre[16 * 256 * 3200];     // [n][ch][t][w] 52.4 MB
__device__ float d_out_pre2[16 * 8 * 128 * 800]; // [n][h][t][ow] 52.4 MB
__device__ float d_G2[8 * 896 * 400];            // fused weights (tf32 bits) 11.5 MB
__device__ float d_xr[16 * 8 * 128 * 400];       // x transposed (tf32 bits) 26.2 MB
__device__ float d_ss[1024];
__device__ float d_rpart[800 * 256];             // res-path BN partials
__device__ float d_mpart[8 * 7 * 16 * 128 * 2];  // main-path BN partials

__device__ __forceinline__ uint32_t f2tf32(float f) {
    uint32_t r;
    asm("cvt.rna.tf32.f32 %0, %1;" : "=r"(r) : "f"(f));
    return r;
}
__device__ __forceinline__ void mma_tf32(float c[4], const uint32_t a[4],
                                         const uint32_t b[2]) {
    asm volatile(
        "mma.sync.aligned.m16n8k8.row.col.f32.tf32.tf32.f32 "
        "{%0,%1,%2,%3},{%4,%5,%6,%7},{%8,%9},{%0,%1,%2,%3};"
        : "+f"(c[0]), "+f"(c[1]), "+f"(c[2]), "+f"(c[3])
        : "r"(a[0]), "r"(a[1]), "r"(a[2]), "r"(a[3]), "r"(b[0]), "r"(b[1]));
}

// ---------------------------------------------------------------------------
// Kernel 1: build BnA and summed bias.
// ---------------------------------------------------------------------------
__global__ void prep_kernel(const int* __restrict__ hop,
                            const float* __restrict__ emb,
                            const float* __restrict__ A,
                            const float* __restrict__ b_block) {
    int g = blockIdx.x;
    int w = threadIdx.x;
    if (g < 24) {
        if (w < 25) {
            const float* eg = emb + g * 12;
            const float* Ag = A + g * 625;
            float sb = 0.f, sa = 0.f;
            for (int v = 0; v < 25; ++v) {
                float bv = eg[hop[v * 25 + w]];
                float av = Ag[v * 25 + w];
                sb += bv * bv;
                sa += av * av;
            }
            float rb = 1.f / (sqrtf(sb) + 1e-4f);
            float ra = 1.f / (sqrtf(sa) + 1e-4f);
            for (int v = 0; v < 25; ++v) {
                float bv = eg[hop[v * 25 + w]];
                float av = Ag[v * 25 + w];
                d_BnA[g * 625 + v * 25 + w] = bv * rb + av * ra;
            }
        }
    } else {
        for (int oc = w; oc < 256; oc += 32)
            d_bsum[oc] = b_block[oc] + b_block[256 + oc] + b_block[512 + oc];
    }
}

// ---------------------------------------------------------------------------
// Kernel 1b: G2[h][o*25+w][c*25+v] = sum_k wg*BnA, stored as tf32 BITS.
// ---------------------------------------------------------------------------
__global__ __launch_bounds__(256) void gbuild_kernel(
    const float* __restrict__ w_block) {
    int o = blockIdx.x;   // 0..32 (32 = row-pad block)
    int h = blockIdx.y;
    int tid = threadIdx.x;
    if (o == 32) {
        float* dst = d_G2 + (h * 896 + 800) * 400;
        for (int idx = tid; idx < 96 * 400; idx += 256) dst[idx] = 0.f;
        return;
    }
    __shared__ float bna[3 * 625];
    __shared__ float wg3[48];
    for (int idx = tid; idx < 1875; idx += 256) {
        int k = idx / 625;
        bna[idx] = d_BnA[(k * 8 + h) * 625 + (idx - k * 625)];
    }
    if (tid < 48) {
        int k = tid / 16, c = tid & 15;
        wg3[tid] = w_block[(k * 8 + h) * 512 + o * 16 + c];
    }
    __syncthreads();
    float* dst = d_G2 + (h * 896 + o * 25) * 400;
    for (int idx = tid; idx < 10000; idx += 256) {   // 25 w x 400 cv
        int w = idx / 400, cv = idx - w * 400;
        int c = cv / 25, v = cv - c * 25;
        int vw = v * 25 + w;
        float val = wg3[c] * bna[vw] + wg3[16 + c] * bna[625 + vw] +
                    wg3[32 + c] * bna[1250 + vw];
        dst[w * 400 + cv] = __uint_as_float(f2tf32(val));
    }
}

// ---------------------------------------------------------------------------
// Kernel 1c: transpose x -> d_xr[n][h][t][c*25+v] as tf32 BITS.
// ---------------------------------------------------------------------------
__global__ __launch_bounds__(256) void xr_kernel(const float* __restrict__ x) {
    int n = blockIdx.x, h = blockIdx.y;
    int tid = threadIdx.x;
    const float* xb = x + n * CTV + h * 16 * TV;
    float* dst = d_xr + (n * 8 + h) * 128 * 400;
#pragma unroll
    for (int it = 0; it < 200; ++it) {
        int idx = it * 256 + tid;            // 0..51199
        int t = idx / 400, j = idx - t * 400;
        int c = j / 25, v = j - c * 25;
        dst[idx] = __uint_as_float(f2tf32(xb[c * TV + t * 25 + v]));
    }
}

// ---------------------------------------------------------------------------
// Kernel 2: res GEMM on mma.sync tf32, v2: K chunked by 64 -> smem 70 KB,
// 2 CTAs/SM. Strides 68 (conflict-free: (4*gid+tg) mod 32 unique).
// ---------------------------------------------------------------------------
#define RES_SMEM_BYTES ((8704 + 8704 + 512) * 4)

__global__ __launch_bounds__(256, 2) void res_gemm_tc(
    const float* __restrict__ x,
    const float* __restrict__ res_w,
    const float* __restrict__ res_b) {
    extern __shared__ __align__(16) float smem[];
    float* As = smem;            // [o(128)][68]
    float* Bs = smem + 8704;     // [tv(128)][68]
    float* part = smem + 17408;  // [2][128][2]

    const int tid = threadIdx.x;
    const int wid = tid >> 5, lane = tid & 31;
    const int gid = lane >> 2, tg = lane & 3;
    const int warp_m = wid >> 1;
    const int warp_n = wid & 1;
    const int tv0 = blockIdx.x * 128;
    const int o0 = blockIdx.y * 128;
    const int n = blockIdx.z;

    float c[2][8][4];
#pragma unroll
    for (int mt = 0; mt < 2; ++mt)
#pragma unroll
        for (int nt = 0; nt < 8; ++nt)
#pragma unroll
            for (int q = 0; q < 4; ++q) c[mt][nt][q] = 0.f;

    const uint32_t* Au = (const uint32_t*)As;
    const uint32_t* Bu = (const uint32_t*)Bs;
    const int arow = (warp_m * 32 + gid) * 68 + tg;
    const int brow = (warp_n * 64 + gid) * 68 + tg;
    const float4* wsrc = (const float4*)(res_w + o0 * 128);
    const float* xn = x + n * CTV + tv0;

    for (int q = 0; q < 2; ++q) {
        const int c0 = q * 64;
        __syncthreads();
        // Stage A: res_w[o][c0..c0+63] -> As[o][cc], float4 + cvt
#pragma unroll
        for (int it = 0; it < 8; ++it) {
            int idx = tid + it * 256;            // 0..2047
            int o = idx >> 4, c4 = idx & 15;
            float4 v = wsrc[o * 32 + (c0 >> 2) + c4];
            uint4 t;
            t.x = f2tf32(v.x); t.y = f2tf32(v.y);
            t.z = f2tf32(v.z); t.w = f2tf32(v.w);
            *(uint4*)(As + o * 68 + c4 * 4) = t;
        }
        // Stage B: x[c0+cc][tv] -> Bs[tv][cc] (transpose scatter)
#pragma unroll
        for (int it = 0; it < 8; ++it) {
            int idx = tid + it * 256;            // 0..2047
            int cc = idx >> 5, j4 = idx & 31;
            float4 v = *(const float4*)(xn + (c0 + cc) * TV + j4 * 4);
            uint32_t* b = (uint32_t*)Bs;
            b[(j4 * 4 + 0) * 68 + cc] = f2tf32(v.x);
            b[(j4 * 4 + 1) * 68 + cc] = f2tf32(v.y);
            b[(j4 * 4 + 2) * 68 + cc] = f2tf32(v.z);
            b[(j4 * 4 + 3) * 68 + cc] = f2tf32(v.w);
        }
        __syncthreads();

#pragma unroll
        for (int step = 0; step < 8; ++step) {
            const int k0 = step * 8;
            uint32_t a[2][4], b[8][2];
#pragma unroll
            for (int mt = 0; mt < 2; ++mt) {
                int base = arow + mt * 16 * 68 + k0;
                a[mt][0] = Au[base];
                a[mt][1] = Au[base + 8 * 68];
                a[mt][2] = Au[base + 4];
                a[mt][3] = Au[base + 8 * 68 + 4];
            }
#pragma unroll
            for (int nt = 0; nt < 8; ++nt) {
                int base = brow + nt * 8 * 68 + k0;
                b[nt][0] = Bu[base];
                b[nt][1] = Bu[base + 4];
            }
#pragma unroll
            for (int mt = 0; mt < 2; ++mt)
#pragma unroll
                for (int nt = 0; nt < 8; ++nt)
                    mma_tf32(c[mt][nt], a[mt], b[nt]);
        }
    }

    const int colbase = tv0 + warp_n * 64 + 2 * tg;
#pragma unroll
    for (int mt = 0; mt < 2; ++mt) {
        int row0 = o0 + warp_m * 32 + mt * 16 + gid;
        float bias0 = res_b[row0];
        float bias1 = res_b[row0 + 8];
        float s0 = 0.f, q0 = 0.f, s1 = 0.f, q1 = 0.f;
        float* dst0 = d_res_pre + (n * 256 + row0) * TV;
        float* dst1 = dst0 + 8 * TV;
#pragma unroll
        for (int nt = 0; nt < 8; ++nt) {
            float v0 = c[mt][nt][0] + bias0;
            float v1 = c[mt][nt][1] + bias0;
            float v2 = c[mt][nt][2] + bias1;
            float v3 = c[mt][nt][3] + bias1;
            s0 += v0 + v1;  q0 += v0 * v0 + v1 * v1;
            s1 += v2 + v3;  q1 += v2 * v2 + v3 * v3;
            int col = colbase + nt * 8;
            *(float2*)(dst0 + col) = make_float2(v0, v1);
            *(float2*)(dst1 + col) = make_float2(v2, v3);
        }
#pragma unroll
        for (int off = 1; off <= 2; off <<= 1) {
            s0 += __shfl_xor_sync(0xFFFFFFFFu, s0, off);
            q0 += __shfl_xor_sync(0xFFFFFFFFu, q0, off);
            s1 += __shfl_xor_sync(0xFFFFFFFFu, s1, off);
            q1 += __shfl_xor_sync(0xFFFFFFFFu, q1, off);
        }
        if (tg == 0) {
            int r = warp_m * 32 + mt * 16 + gid;
            part[(warp_n * 128 + r) * 2] = s0;
            part[(warp_n * 128 + r) * 2 + 1] = q0;
            part[(warp_n * 128 + r + 8) * 2] = s1;
            part[(warp_n * 128 + r + 8) * 2 + 1] = q1;
        }
    }
    __syncthreads();
    if (tid < 128) {
        float s = part[tid * 2] + part[(128 + tid) * 2];
        float q = part[tid * 2 + 1] + part[(128 + tid) * 2 + 1];
        int blk = (n * 2 + blockIdx.y) * 25 + blockIdx.x;
        d_rpart[blk * 256 + tid * 2] = s;
        d_rpart[blk * 256 + tid * 2 + 1] = q;
    }
}

// ---------------------------------------------------------------------------
// Kernel 3: main fused GEMM (validated round 6, unchanged).
// ---------------------------------------------------------------------------
#define MAIN_SMEM_BYTES ((10752 + 10752 + 512) * 4)

__global__ __launch_bounds__(256, 2) void main_gemm_tc() {
    extern __shared__ __align__(16) float smem[];
    float* As = smem;            // [128 rows][84]
    float* Bs = smem + 10752;    // [128 t][84]
    float* part = smem + 21504;  // [2][128][2]

    const int tid = threadIdx.x;
    const int wid = tid >> 5, lane = tid & 31;
    const int gid = lane >> 2, tg = lane & 3;
    const int warp_m = wid >> 1;
    const int warp_n = wid & 1;
    const int n = blockIdx.x;
    const int mb = blockIdx.y;
    const int m0 = mb * 128;
    const int h = blockIdx.z;

    float c[2][8][4];
#pragma unroll
    for (int mt = 0; mt < 2; ++mt)
#pragma unroll
        for (int nt = 0; nt < 8; ++nt)
#pragma unroll
            for (int q = 0; q < 4; ++q) c[mt][nt][q] = 0.f;

    const uint32_t* Au = (const uint32_t*)As;
    const uint32_t* Bu = (const uint32_t*)Bs;
    const int arow = (warp_m * 32 + gid) * 84 + tg;
    const int brow = (warp_n * 64 + gid) * 84 + tg;
    const float* gbase = d_G2 + (h * 896 + m0) * 400;
    const float* xbase = d_xr + (n * 8 + h) * 128 * 400;

    for (int q = 0; q < 5; ++q) {
        const int kc0 = q * 80;
        __syncthreads();
#pragma unroll
        for (int it = 0; it < 10; ++it) {
            int idx = tid + it * 256;            // 0..2559
            int row = idx / 20, f = idx - row * 20;
            *(float4*)(As + row * 84 + f * 4) =
                *(const float4*)(gbase + row * 400 + kc0 + f * 4);
        }
#pragma unroll
        for (int it = 0; it < 10; ++it) {
            int idx = tid + it * 256;
            int row = idx / 20, f = idx - row * 20;
            *(float4*)(Bs + row * 84 + f * 4) =
                *(const float4*)(xbase + row * 400 + kc0 + f * 4);
        }
        __syncthreads();

#pragma unroll
        for (int step = 0; step < 10; ++step) {
            const int k0 = step * 8;
            uint32_t a[2][4], b[8][2];
#pragma unroll
            for (int mt = 0; mt < 2; ++mt) {
                int base = arow + mt * 16 * 84 + k0;
                a[mt][0] = Au[base];
                a[mt][1] = Au[base + 8 * 84];
                a[mt][2] = Au[base + 4];
                a[mt][3] = Au[base + 8 * 84 + 4];
            }
#pragma unroll
            for (int nt = 0; nt < 8; ++nt) {
                int base = brow + nt * 8 * 84 + k0;
                b[nt][0] = Bu[base];
                b[nt][1] = Bu[base + 4];
            }
#pragma unroll
            for (int mt = 0; mt < 2; ++mt)
#pragma unroll
                for (int nt = 0; nt < 8; ++nt)
                    mma_tf32(c[mt][nt], a[mt], b[nt]);
        }
    }

    // Epilogue: bias, coalesced store to [n][h][t][ow], BN partials.
    float* obase = d_out_pre2 + (n * 8 + h) * 128 * 800;
#pragma unroll
    for (int mt = 0; mt < 2; ++mt) {
        int r0 = m0 + warp_m * 32 + mt * 16 + gid;
        int o0 = r0 / 25, o1 = (r0 + 8) / 25;
        float bias0 = (r0 < 800) ? d_bsum[h * 32 + o0] : 0.f;
        float bias1 = (r0 + 8 < 800) ? d_bsum[h * 32 + o1] : 0.f;
        float s0 = 0.f, q0 = 0.f, s1 = 0.f, q1 = 0.f;
        int colbase = warp_n * 64 + 2 * tg;
#pragma unroll
        for (int nt = 0; nt < 8; ++nt) {
            float v0 = c[mt][nt][0] + bias0;
            float v1 = c[mt][nt][1] + bias0;
            float v2 = c[mt][nt][2] + bias1;
            float v3 = c[mt][nt][3] + bias1;
            s0 += v0 + v1;  q0 += v0 * v0 + v1 * v1;
            s1 += v2 + v3;  q1 += v2 * v2 + v3 * v3;
            int col = colbase + nt * 8;
            if (r0 < 800) {
                obase[col * 800 + r0] = v0;
                obase[(col + 1) * 800 + r0] = v1;
            }
            if (r0 + 8 < 800) {
                obase[col * 800 + r0 + 8] = v2;
                obase[(col + 1) * 800 + r0 + 8] = v3;
            }
        }
#pragma unroll
        for (int off = 1; off <= 2; off <<= 1) {
            s0 += __shfl_xor_sync(0xFFFFFFFFu, s0, off);
            q0 += __shfl_xor_sync(0xFFFFFFFFu, q0, off);
            s1 += __shfl_xor_sync(0xFFFFFFFFu, s1, off);
            q1 += __shfl_xor_sync(0xFFFFFFFFu, q1, off);
        }
        if (tg == 0) {
            int r = warp_m * 32 + mt * 16 + gid;
            part[(warp_n * 128 + r) * 2] = s0;
            part[(warp_n * 128 + r) * 2 + 1] = q0;
            part[(warp_n * 128 + r + 8) * 2] = s1;
            part[(warp_n * 128 + r + 8) * 2 + 1] = q1;
        }
    }
    __syncthreads();
    if (tid < 128) {
        float s = part[tid * 2] + part[(128 + tid) * 2];
        float q = part[tid * 2 + 1] + part[(128 + tid) * 2 + 1];
        int blk = (h * 7 + mb) * 16 + n;
        d_mpart[(blk * 128 + tid) * 2] = s;
        d_mpart[(blk * 128 + tid) * 2 + 1] = q;
    }
}

// ---------------------------------------------------------------------------
// Kernel 4a: out-path BN stats from GEMM partials.
// ---------------------------------------------------------------------------
__global__ __launch_bounds__(128) void stats_out_kernel(
    const float* __restrict__ bn_gamma, const float* __restrict__ bn_beta) {
    __shared__ float ssum[128];
    __shared__ float ssq[128];
    int ch = blockIdx.x;
    int h = ch >> 5, o = ch & 31;
    int tid = threadIdx.x;

    float s = 0.f, q = 0.f;
    for (int e = tid; e < 400; e += 128) {
        int w = e >> 4, nn = e & 15;
        int grow = o * 25 + w;
        int mb = grow >> 7, lr = grow & 127;
        int blk = (h * 7 + mb) * 16 + nn;
        s += d_mpart[(blk * 128 + lr) * 2];
        q += d_mpart[(blk * 128 + lr) * 2 + 1];
    }
    ssum[tid] = s;
    ssq[tid] = q;
    __syncthreads();
    for (int st = 64; st > 0; st >>= 1) {
        if (tid < st) {
            ssum[tid] += ssum[tid + st];
            ssq[tid] += ssq[tid + st];
        }
        __syncthreads();
    }
    if (tid == 0) {
        const float inv = 1.f / 51200.f;
        float mean = ssum[0] * inv;
        float var = ssq[0] * inv - mean * mean;
        float sc = bn_gamma[ch] * rsqrtf(var + 1e-5f);
        d_ss[ch] = sc;
        d_ss[256 + ch] = bn_beta[ch] - mean * sc;
    }
}

// ---------------------------------------------------------------------------
// Kernel 4b: res-path BN stats from GEMM partials.
// ---------------------------------------------------------------------------
__global__ __launch_bounds__(128) void stats_res_kernel(
    const float* __restrict__ res_bn_gamma, const float* __restrict__ res_bn_beta) {
    __shared__ float ssum[128];
    __shared__ float ssq[128];
    int ch = blockIdx.x;
    int ob = ch >> 7, row = ch & 127;
    int tid = threadIdx.x;

    float s = 0.f, q = 0.f;
    for (int e = tid; e < 400; e += 128) {
        int nn = e / 25, tvb = e - nn * 25;
        int blk = (nn * 2 + ob) * 25 + tvb;
        s += d_rpart[blk * 256 + row * 2];
        q += d_rpart[blk * 256 + row * 2 + 1];
    }
    ssum[tid] = s;
    ssq[tid] = q;
    __syncthreads();
    for (int st = 64; st > 0; st >>= 1) {
        if (tid < st) {
            ssum[tid] += ssum[tid + st];
            ssq[tid] += ssq[tid + st];
        }
        __syncthreads();
    }
    if (tid == 0) {
        const float inv = 1.f / 51200.f;
        float mean = ssum[0] * inv;
        float var = ssq[0] * inv - mean * mean;
        float sc = res_bn_gamma[ch] * rsqrtf(var + 1e-5f);
        d_ss[512 + ch] = sc;
        d_ss[768 + ch] = res_bn_beta[ch] - mean * sc;
    }
}

// ---------------------------------------------------------------------------
// Kernel 5: out = relu(BN(out_pre2) + BN(res_pre)). One block per (n,t).
// ---------------------------------------------------------------------------
__global__ __launch_bounds__(256) void final_kernel(float* __restrict__ out) {
    int b = blockIdx.x;
    int n = b >> 7, t = b & 127;
    int tid = threadIdx.x;
    const float* p2 = d_out_pre2 + (n * 8) * 128 * 800 + t * 800;
#pragma unroll
    for (int it = 0; it < 25; ++it) {
        int idx = it * 256 + tid;          // 0..6399
        int ch = idx / 25, w = idx - ch * 25;
        int h = ch >> 5, o = ch & 31;
        float op = p2[h * 128 * 800 + o * 25 + w];
        float rp = d_res_pre[((n * 256 + ch) * 128 + t) * 25 + w];
        float so = d_ss[ch], ho = d_ss[256 + ch];
        float sr = d_ss[512 + ch], hr = d_ss[768 + ch];
        float r = fmaxf(fmaf(op, so, ho) + fmaf(rp, sr, hr), 0.f);
        out[((n * 256 + ch) * 128 + t) * 25 + w] = r;
    }
}

// ---------------------------------------------------------------------------
extern "C" void kernel_launch(void* const* d_in, const int* in_sizes, int n_in,
                              void* d_out, int out_size) {
    const float* x            = (const float*)d_in[0];
    const int*   hop          = (const int*)d_in[1];
    const float* emb          = (const float*)d_in[2];
    const float* A            = (const float*)d_in[3];
    const float* w_block      = (const float*)d_in[4];
    const float* b_block      = (const float*)d_in[5];
    const float* bn_gamma     = (const float*)d_in[6];
    const float* bn_beta      = (const float*)d_in[7];
    const float* res_w        = (const float*)d_in[8];
    const float* res_b        = (const float*)d_in[9];
    const float* res_bn_gamma = (const float*)d_in[10];
    const float* res_bn_beta  = (const float*)d_in[11];
    float* out = (float*)d_out;

    cudaFuncSetAttribute(res_gemm_tc, cudaFuncAttributeMaxDynamicSharedMemorySize,
                         RES_SMEM_BYTES);
    cudaFuncSetAttribute(main_gemm_tc, cudaFuncAttributeMaxDynamicSharedMemorySize,
                         MAIN_SMEM_BYTES);

    prep_kernel<<<25, 32>>>(hop, emb, A, b_block);
    gbuild_kernel<<<dim3(33, 8), 256>>>(w_block);
    xr_kernel<<<dim3(16, 8), 256>>>(x);
    res_gemm_tc<<<dim3(25, 2, 16), 256, RES_SMEM_BYTES>>>(x, res_w, res_b);
    main_gemm_tc<<<dim3(16, 7, 8), 256, MAIN_SMEM_BYTES>>>();
    stats_out_kernel<<<256, 128>>>(bn_gamma, bn_beta);
    stats_res_kernel<<<256, 128>>>(res_bn_gamma, res_bn_beta);
    final_kernel<<<2048, 256>>>(out);
}

// round 8
// speedup vs baseline: 1.6306x; 1.3032x over previous
#include <cuda_runtime.h>
#include <cuda_fp16.h>
#include <math.h>
#include <stdint.h>

// Problem constants
// N=16, C=128, T=128, V=25, K=3, H=8, OC=256, C/H=16, OC/H=32
// x: (16,128,128,25)  out: (16,256,128,25)

#define TV 3200          // T*V
#define CTV 409600       // C*T*V

// ---- scratch (device globals; allocation-free) ----
__device__ float d_BnA[24 * 625];
__device__ float d_bsum[256];
__device__ float d_res_pre[16 * 256 * 3200];     // [n][ch][t][w] 52.4 MB
__device__ float d_out_pre2[16 * 8 * 128 * 800]; // [n][h][t][ow] 52.4 MB
__device__ __align__(16) __half d_G2h[8 * 896 * 400];   // fused weights fp16
__device__ __align__(16) __half d_xrh[16 * 8 * 128 * 400]; // x for main GEMM
__device__ __align__(16) __half d_xth[16 * 3200 * 128];    // x for res GEMM
__device__ __align__(16) __half d_rwh[256 * 128];          // res_w fp16
__device__ float d_ss[1024];
__device__ float d_rpart[800 * 256];             // res-path BN partials
__device__ float d_mpart[8 * 7 * 16 * 128 * 2];  // main-path BN partials

__device__ __forceinline__ void mma_f16(float c[4], const uint32_t a[4],
                                        const uint32_t b[2]) {
    asm volatile(
        "mma.sync.aligned.m16n8k16.row.col.f32.f16.f16.f32 "
        "{%0,%1,%2,%3},{%4,%5,%6,%7},{%8,%9},{%0,%1,%2,%3};"
        : "+f"(c[0]), "+f"(c[1]), "+f"(c[2]), "+f"(c[3])
        : "r"(a[0]), "r"(a[1]), "r"(a[2]), "r"(a[3]), "r"(b[0]), "r"(b[1]));
}

// ---------------------------------------------------------------------------
// Kernel 1: build BnA and summed bias.
// ---------------------------------------------------------------------------
__global__ void prep_kernel(const int* __restrict__ hop,
                            const float* __restrict__ emb,
                            const float* __restrict__ A,
                            const float* __restrict__ b_block) {
    int g = blockIdx.x;
    int w = threadIdx.x;
    if (g < 24) {
        if (w < 25) {
            const float* eg = emb + g * 12;
            const float* Ag = A + g * 625;
            float sb = 0.f, sa = 0.f;
            for (int v = 0; v < 25; ++v) {
                float bv = eg[hop[v * 25 + w]];
                float av = Ag[v * 25 + w];
                sb += bv * bv;
                sa += av * av;
            }
            float rb = 1.f / (sqrtf(sb) + 1e-4f);
            float ra = 1.f / (sqrtf(sa) + 1e-4f);
            for (int v = 0; v < 25; ++v) {
                float bv = eg[hop[v * 25 + w]];
                float av = Ag[v * 25 + w];
                d_BnA[g * 625 + v * 25 + w] = bv * rb + av * ra;
            }
        }
    } else {
        for (int oc = w; oc < 256; oc += 32)
            d_bsum[oc] = b_block[oc] + b_block[256 + oc] + b_block[512 + oc];
    }
}

// ---------------------------------------------------------------------------
// Kernel 1a: convert res_w -> fp16.
// ---------------------------------------------------------------------------
__global__ __launch_bounds__(256) void cvt_resw_kernel(
    const float* __restrict__ res_w) {
    int idx = (blockIdx.x * 256 + threadIdx.x) * 4;
    float4 v = *(const float4*)(res_w + idx);
    __half2* dst = (__half2*)(d_rwh + idx);
    dst[0] = __floats2half2_rn(v.x, v.y);
    dst[1] = __floats2half2_rn(v.z, v.w);
}

// ---------------------------------------------------------------------------
// Kernel 1b: G2h[h][o*25+w][c*25+v] = sum_k wg*BnA, fp16.
// ---------------------------------------------------------------------------
__global__ __launch_bounds__(256) void gbuild_kernel(
    const float* __restrict__ w_block) {
    int o = blockIdx.x;   // 0..32 (32 = row-pad block)
    int h = blockIdx.y;
    int tid = threadIdx.x;
    if (o == 32) {
        __half* dst = d_G2h + (h * 896 + 800) * 400;
        for (int idx = tid; idx < 96 * 400; idx += 256) dst[idx] = __half(0.f);
        return;
    }
    __shared__ float bna[3 * 625];
    __shared__ float wg3[48];
    for (int idx = tid; idx < 1875; idx += 256) {
        int k = idx / 625;
        bna[idx] = d_BnA[(k * 8 + h) * 625 + (idx - k * 625)];
    }
    if (tid < 48) {
        int k = tid / 16, c = tid & 15;
        wg3[tid] = w_block[(k * 8 + h) * 512 + o * 16 + c];
    }
    __syncthreads();
    __half* dst = d_G2h + (h * 896 + o * 25) * 400;
    for (int idx = tid; idx < 10000; idx += 256) {   // 25 w x 400 cv
        int w = idx / 400, cv = idx - w * 400;
        int c = cv / 25, v = cv - c * 25;
        int vw = v * 25 + w;
        float val = wg3[c] * bna[vw] + wg3[16 + c] * bna[625 + vw] +
                    wg3[32 + c] * bna[1250 + vw];
        dst[w * 400 + cv] = __float2half_rn(val);
    }
}

// ---------------------------------------------------------------------------
// Kernel 1c: build d_xrh[n][h][t][c*25+v] and d_xth[n][tv][h*16+c] (fp16).
// ---------------------------------------------------------------------------
__global__ __launch_bounds__(256) void xbuild_kernel(const float* __restrict__ x) {
    __shared__ float xs[16 * 132];
    int n = blockIdx.x, h = blockIdx.y;
    int tid = threadIdx.x;
    const float* xb = x + n * CTV + h * 16 * TV;

    // xth via smem tile transpose: 25 tiles of 128 tv
    for (int tile = 0; tile < 25; ++tile) {
        int tv0 = tile * 128;
        __syncthreads();
#pragma unroll
        for (int it = 0; it < 8; ++it) {
            int idx = tid + it * 256;            // 0..2047
            int cc = idx >> 7, j = idx & 127;
            xs[cc * 132 + j] = xb[cc * TV + tv0 + j];
        }
        __syncthreads();
#pragma unroll
        for (int it = 0; it < 4; ++it) {
            int idx = tid + it * 256;            // 0..1023
            int tvl = idx >> 3, ccp = idx & 7;
            __half2 hv = __floats2half2_rn(xs[(2 * ccp) * 132 + tvl],
                                           xs[(2 * ccp + 1) * 132 + tvl]);
            *(__half2*)(d_xth + (n * 3200 + tv0 + tvl) * 128 + h * 16 + ccp * 2) = hv;
        }
    }
    // xrh: [t][c*25+v]
    __half* dstr = d_xrh + (n * 8 + h) * 128 * 400;
#pragma unroll
    for (int it = 0; it < 200; ++it) {
        int idx = it * 256 + tid;                // 0..51199
        int t = idx / 400, j = idx - t * 400;
        int c = j / 25, v = j - c * 25;
        dstr[idx] = __float2half_rn(xb[c * TV + t * 25 + v]);
    }
}

// ---------------------------------------------------------------------------
// Kernel 2: res GEMM fp16 m16n8k16. Single K-stage (K=128 halves).
// smem stride 136 halves (68 words, conflict-free). 2 CTAs/SM.
// A = rwh rows (m=o), B = xth rows (n=tv). Epilogue unchanged from r4.
// ---------------------------------------------------------------------------
#define RES_SMEM_BYTES (34816 * 2 + 2048)

__global__ __launch_bounds__(256, 2) void res_gemm_tc(
    const float* __restrict__ res_b) {
    extern __shared__ __align__(16) char smem[];
    __half* As = (__half*)smem;                 // [o 128][136]
    __half* Bs = (__half*)(smem + 34816);       // [tv 128][136]
    float* part = (float*)(smem + 69632);

    const int tid = threadIdx.x;
    const int wid = tid >> 5, lane = tid & 31;
    const int gid = lane >> 2, tg = lane & 3;
    const int warp_m = wid >> 1;
    const int warp_n = wid & 1;
    const int tv0 = blockIdx.x * 128;
    const int o0 = blockIdx.y * 128;
    const int n = blockIdx.z;

    // Stage A: rwh[o0+row][0..127] -> As (uint4 copies)
    {
        const uint4* src = (const uint4*)(d_rwh + o0 * 128);
#pragma unroll
        for (int it = 0; it < 8; ++it) {
            int idx = tid + it * 256;            // 0..2047
            int row = idx >> 4, f = idx & 15;
            *(uint4*)(As + row * 136 + f * 8) = src[row * 16 + f];
        }
    }
    // Stage B: xth[n][tv0+row][0..127] -> Bs
    {
        const uint4* src = (const uint4*)(d_xth + (n * 3200 + tv0) * 128);
#pragma unroll
        for (int it = 0; it < 8; ++it) {
            int idx = tid + it * 256;
            int row = idx >> 4, f = idx & 15;
            *(uint4*)(Bs + row * 136 + f * 8) = src[row * 16 + f];
        }
    }
    __syncthreads();

    float c[2][8][4];
#pragma unroll
    for (int mt = 0; mt < 2; ++mt)
#pragma unroll
        for (int nt = 0; nt < 8; ++nt)
#pragma unroll
            for (int q = 0; q < 4; ++q) c[mt][nt][q] = 0.f;

    const uint32_t* Au = (const uint32_t*)As;
    const uint32_t* Bu = (const uint32_t*)Bs;
    const int arow = (warp_m * 32 + gid) * 68 + tg;
    const int brow = (warp_n * 64 + gid) * 68 + tg;

#pragma unroll
    for (int step = 0; step < 8; ++step) {
        const int k0 = step * 8;                 // words (16 halves per step)
        uint32_t a[2][4], b[8][2];
#pragma unroll
        for (int mt = 0; mt < 2; ++mt) {
            int base = arow + mt * 16 * 68 + k0;
            a[mt][0] = Au[base];
            a[mt][1] = Au[base + 8 * 68];
            a[mt][2] = Au[base + 4];
            a[mt][3] = Au[base + 8 * 68 + 4];
        }
#pragma unroll
        for (int nt = 0; nt < 8; ++nt) {
            int base = brow + nt * 8 * 68 + k0;
            b[nt][0] = Bu[base];
            b[nt][1] = Bu[base + 4];
        }
#pragma unroll
        for (int mt = 0; mt < 2; ++mt)
#pragma unroll
            for (int nt = 0; nt < 8; ++nt)
                mma_f16(c[mt][nt], a[mt], b[nt]);
    }

    const int colbase = tv0 + warp_n * 64 + 2 * tg;
#pragma unroll
    for (int mt = 0; mt < 2; ++mt) {
        int row0 = o0 + warp_m * 32 + mt * 16 + gid;
        float bias0 = res_b[row0];
        float bias1 = res_b[row0 + 8];
        float s0 = 0.f, q0 = 0.f, s1 = 0.f, q1 = 0.f;
        float* dst0 = d_res_pre + (n * 256 + row0) * TV;
        float* dst1 = dst0 + 8 * TV;
#pragma unroll
        for (int nt = 0; nt < 8; ++nt) {
            float v0 = c[mt][nt][0] + bias0;
            float v1 = c[mt][nt][1] + bias0;
            float v2 = c[mt][nt][2] + bias1;
            float v3 = c[mt][nt][3] + bias1;
            s0 += v0 + v1;  q0 += v0 * v0 + v1 * v1;
            s1 += v2 + v3;  q1 += v2 * v2 + v3 * v3;
            int col = colbase + nt * 8;
            *(float2*)(dst0 + col) = make_float2(v0, v1);
            *(float2*)(dst1 + col) = make_float2(v2, v3);
        }
#pragma unroll
        for (int off = 1; off <= 2; off <<= 1) {
            s0 += __shfl_xor_sync(0xFFFFFFFFu, s0, off);
            q0 += __shfl_xor_sync(0xFFFFFFFFu, q0, off);
            s1 += __shfl_xor_sync(0xFFFFFFFFu, s1, off);
            q1 += __shfl_xor_sync(0xFFFFFFFFu, q1, off);
        }
        if (tg == 0) {
            int r = warp_m * 32 + mt * 16 + gid;
            part[(warp_n * 128 + r) * 2] = s0;
            part[(warp_n * 128 + r) * 2 + 1] = q0;
            part[(warp_n * 128 + r + 8) * 2] = s1;
            part[(warp_n * 128 + r + 8) * 2 + 1] = q1;
        }
    }
    __syncthreads();
    if (tid < 128) {
        float s = part[tid * 2] + part[(128 + tid) * 2];
        float q = part[tid * 2 + 1] + part[(128 + tid) * 2 + 1];
        int blk = (n * 2 + blockIdx.y) * 25 + blockIdx.x;
        d_rpart[blk * 256 + tid * 2] = s;
        d_rpart[blk * 256 + tid * 2 + 1] = q;
    }
}

// ---------------------------------------------------------------------------
// Kernel 3: main fused GEMM fp16. K=400 halves, 5 chunks of 80.
// smem stride 88 halves (44 words, conflict-free). Epilogue unchanged.
// ---------------------------------------------------------------------------
#define MAIN_SMEM_BYTES (22528 * 2 + 2048)

__global__ __launch_bounds__(256, 2) void main_gemm_tc() {
    extern __shared__ __align__(16) char smem[];
    __half* As = (__half*)smem;                 // [128 rows][88]
    __half* Bs = (__half*)(smem + 22528);       // [128 t][88]
    float* part = (float*)(smem + 45056);

    const int tid = threadIdx.x;
    const int wid = tid >> 5, lane = tid & 31;
    const int gid = lane >> 2, tg = lane & 3;
    const int warp_m = wid >> 1;
    const int warp_n = wid & 1;
    const int n = blockIdx.x;
    const int mb = blockIdx.y;
    const int m0 = mb * 128;
    const int h = blockIdx.z;

    float c[2][8][4];
#pragma unroll
    for (int mt = 0; mt < 2; ++mt)
#pragma unroll
        for (int nt = 0; nt < 8; ++nt)
#pragma unroll
            for (int q = 0; q < 4; ++q) c[mt][nt][q] = 0.f;

    const uint32_t* Au = (const uint32_t*)As;
    const uint32_t* Bu = (const uint32_t*)Bs;
    const int arow = (warp_m * 32 + gid) * 44 + tg;
    const int brow = (warp_n * 64 + gid) * 44 + tg;
    const __half* gbase = d_G2h + (h * 896 + m0) * 400;
    const __half* xbase = d_xrh + (n * 8 + h) * 128 * 400;

    for (int q = 0; q < 5; ++q) {
        const int kc0 = q * 80;                  // halves
        __syncthreads();
#pragma unroll
        for (int it = 0; it < 5; ++it) {
            int idx = tid + it * 256;            // 0..1279
            int row = idx / 10, f = idx - row * 10;
            *(uint4*)(As + row * 88 + f * 8) =
                *(const uint4*)(gbase + row * 400 + kc0 + f * 8);
        }
#pragma unroll
        for (int it = 0; it < 5; ++it) {
            int idx = tid + it * 256;
            int row = idx / 10, f = idx - row * 10;
            *(uint4*)(Bs + row * 88 + f * 8) =
                *(const uint4*)(xbase + row * 400 + kc0 + f * 8);
        }
        __syncthreads();

#pragma unroll
        for (int step = 0; step < 5; ++step) {
            const int k0 = step * 8;             // words
            uint32_t a[2][4], b[8][2];
#pragma unroll
            for (int mt = 0; mt < 2; ++mt) {
                int base = arow + mt * 16 * 44 + k0;
                a[mt][0] = Au[base];
                a[mt][1] = Au[base + 8 * 44];
                a[mt][2] = Au[base + 4];
                a[mt][3] = Au[base + 8 * 44 + 4];
            }
#pragma unroll
            for (int nt = 0; nt < 8; ++nt) {
                int base = brow + nt * 8 * 44 + k0;
                b[nt][0] = Bu[base];
                b[nt][1] = Bu[base + 4];
            }
#pragma unroll
            for (int mt = 0; mt < 2; ++mt)
#pragma unroll
                for (int nt = 0; nt < 8; ++nt)
                    mma_f16(c[mt][nt], a[mt], b[nt]);
        }
    }

    // Epilogue: bias, coalesced store to [n][h][t][ow], BN partials.
    float* obase = d_out_pre2 + (n * 8 + h) * 128 * 800;
#pragma unroll
    for (int mt = 0; mt < 2; ++mt) {
        int r0 = m0 + warp_m * 32 + mt * 16 + gid;
        int o0 = r0 / 25, o1 = (r0 + 8) / 25;
        float bias0 = (r0 < 800) ? d_bsum[h * 32 + o0] : 0.f;
        float bias1 = (r0 + 8 < 800) ? d_bsum[h * 32 + o1] : 0.f;
        float s0 = 0.f, q0 = 0.f, s1 = 0.f, q1 = 0.f;
        int colbase = warp_n * 64 + 2 * tg;
#pragma unroll
        for (int nt = 0; nt < 8; ++nt) {
            float v0 = c[mt][nt][0] + bias0;
            float v1 = c[mt][nt][1] + bias0;
            float v2 = c[mt][nt][2] + bias1;
            float v3 = c[mt][nt][3] + bias1;
            s0 += v0 + v1;  q0 += v0 * v0 + v1 * v1;
            s1 += v2 + v3;  q1 += v2 * v2 + v3 * v3;
            int col = colbase + nt * 8;
            if (r0 < 800) {
                obase[col * 800 + r0] = v0;
                obase[(col + 1) * 800 + r0] = v1;
            }
            if (r0 + 8 < 800) {
                obase[col * 800 + r0 + 8] = v2;
                obase[(col + 1) * 800 + r0 + 8] = v3;
            }
        }
#pragma unroll
        for (int off = 1; off <= 2; off <<= 1) {
            s0 += __shfl_xor_sync(0xFFFFFFFFu, s0, off);
            q0 += __shfl_xor_sync(0xFFFFFFFFu, q0, off);
            s1 += __shfl_xor_sync(0xFFFFFFFFu, s1, off);
            q1 += __shfl_xor_sync(0xFFFFFFFFu, q1, off);
        }
        if (tg == 0) {
            int r = warp_m * 32 + mt * 16 + gid;
            part[(warp_n * 128 + r) * 2] = s0;
            part[(warp_n * 128 + r) * 2 + 1] = q0;
            part[(warp_n * 128 + r + 8) * 2] = s1;
            part[(warp_n * 128 + r + 8) * 2 + 1] = q1;
        }
    }
    __syncthreads();
    if (tid < 128) {
        float s = part[tid * 2] + part[(128 + tid) * 2];
        float q = part[tid * 2 + 1] + part[(128 + tid) * 2 + 1];
        int blk = (h * 7 + mb) * 16 + n;
        d_mpart[(blk * 128 + tid) * 2] = s;
        d_mpart[(blk * 128 + tid) * 2 + 1] = q;
    }
}

// ---------------------------------------------------------------------------
// Kernel 4a: out-path BN stats from GEMM partials.
// ---------------------------------------------------------------------------
__global__ __launch_bounds__(128) void stats_out_kernel(
    const float* __restrict__ bn_gamma, const float* __restrict__ bn_beta) {
    __shared__ float ssum[128];
    __shared__ float ssq[128];
    int ch = blockIdx.x;
    int h = ch >> 5, o = ch & 31;
    int tid = threadIdx.x;

    float s = 0.f, q = 0.f;
    for (int e = tid; e < 400; e += 128) {
        int w = e >> 4, nn = e & 15;
        int grow = o * 25 + w;
        int mb = grow >> 7, lr = grow & 127;
        int blk = (h * 7 + mb) * 16 + nn;
        s += d_mpart[(blk * 128 + lr) * 2];
        q += d_mpart[(blk * 128 + lr) * 2 + 1];
    }
    ssum[tid] = s;
    ssq[tid] = q;
    __syncthreads();
    for (int st = 64; st > 0; st >>= 1) {
        if (tid < st) {
            ssum[tid] += ssum[tid + st];
            ssq[tid] += ssq[tid + st];
        }
        __syncthreads();
    }
    if (tid == 0) {
        const float inv = 1.f / 51200.f;
        float mean = ssum[0] * inv;
        float var = ssq[0] * inv - mean * mean;
        float sc = bn_gamma[ch] * rsqrtf(var + 1e-5f);
        d_ss[ch] = sc;
        d_ss[256 + ch] = bn_beta[ch] - mean * sc;
    }
}

// ---------------------------------------------------------------------------
// Kernel 4b: res-path BN stats from GEMM partials.
// ---------------------------------------------------------------------------
__global__ __launch_bounds__(128) void stats_res_kernel(
    const float* __restrict__ res_bn_gamma, const float* __restrict__ res_bn_beta) {
    __shared__ float ssum[128];
    __shared__ float ssq[128];
    int ch = blockIdx.x;
    int ob = ch >> 7, row = ch & 127;
    int tid = threadIdx.x;

    float s = 0.f, q = 0.f;
    for (int e = tid; e < 400; e += 128) {
        int nn = e / 25, tvb = e - nn * 25;
        int blk = (nn * 2 + ob) * 25 + tvb;
        s += d_rpart[blk * 256 + row * 2];
        q += d_rpart[blk * 256 + row * 2 + 1];
    }
    ssum[tid] = s;
    ssq[tid] = q;
    __syncthreads();
    for (int st = 64; st > 0; st >>= 1) {
        if (tid < st) {
            ssum[tid] += ssum[tid + st];
            ssq[tid] += ssq[tid + st];
        }
        __syncthreads();
    }
    if (tid == 0) {
        const float inv = 1.f / 51200.f;
        float mean = ssum[0] * inv;
        float var = ssq[0] * inv - mean * mean;
        float sc = res_bn_gamma[ch] * rsqrtf(var + 1e-5f);
        d_ss[512 + ch] = sc;
        d_ss[768 + ch] = res_bn_beta[ch] - mean * sc;
    }
}

// ---------------------------------------------------------------------------
// Kernel 5: out = relu(BN(out_pre2) + BN(res_pre)). One block per (n,t).
// ---------------------------------------------------------------------------
__global__ __launch_bounds__(256) void final_kernel(float* __restrict__ out) {
    int b = blockIdx.x;
    int n = b >> 7, t = b & 127;
    int tid = threadIdx.x;
    const float* p2 = d_out_pre2 + (n * 8) * 128 * 800 + t * 800;
#pragma unroll
    for (int it = 0; it < 25; ++it) {
        int idx = it * 256 + tid;          // 0..6399
        int ch = idx / 25, w = idx - ch * 25;
        int h = ch >> 5, o = ch & 31;
        float op = p2[h * 128 * 800 + o * 25 + w];
        float rp = d_res_pre[((n * 256 + ch) * 128 + t) * 25 + w];
        float so = d_ss[ch], ho = d_ss[256 + ch];
        float sr = d_ss[512 + ch], hr = d_ss[768 + ch];
        float r = fmaxf(fmaf(op, so, ho) + fmaf(rp, sr, hr), 0.f);
        out[((n * 256 + ch) * 128 + t) * 25 + w] = r;
    }
}

// ---------------------------------------------------------------------------
extern "C" void kernel_launch(void* const* d_in, const int* in_sizes, int n_in,
                              void* d_out, int out_size) {
    const float* x            = (const float*)d_in[0];
    const int*   hop          = (const int*)d_in[1];
    const float* emb          = (const float*)d_in[2];
    const float* A            = (const float*)d_in[3];
    const float* w_block      = (const float*)d_in[4];
    const float* b_block      = (const float*)d_in[5];
    const float* bn_gamma     = (const float*)d_in[6];
    const float* bn_beta      = (const float*)d_in[7];
    const float* res_w        = (const float*)d_in[8];
    const float* res_b        = (const float*)d_in[9];
    const float* res_bn_gamma = (const float*)d_in[10];
    const float* res_bn_beta  = (const float*)d_in[11];
    float* out = (float*)d_out;

    cudaFuncSetAttribute(res_gemm_tc, cudaFuncAttributeMaxDynamicSharedMemorySize,
                         RES_SMEM_BYTES);
    cudaFuncSetAttribute(main_gemm_tc, cudaFuncAttributeMaxDynamicSharedMemorySize,
                         MAIN_SMEM_BYTES);

    prep_kernel<<<25, 32>>>(hop, emb, A, b_block);
    cvt_resw_kernel<<<32, 256>>>(res_w);
    gbuild_kernel<<<dim3(33, 8), 256>>>(w_block);
    xbuild_kernel<<<dim3(16, 8), 256>>>(x);
    res_gemm_tc<<<dim3(25, 2, 16), 256, RES_SMEM_BYTES>>>(res_b);
    main_gemm_tc<<<dim3(16, 7, 8), 256, MAIN_SMEM_BYTES>>>();
    stats_out_kernel<<<256, 128>>>(bn_gamma, bn_beta);
    stats_res_kernel<<<256, 128>>>(res_bn_gamma, res_bn_beta);
    final_kernel<<<2048, 256>>>(out);
}

// round 9
// speedup vs baseline: 1.8650x; 1.1437x over previous
#include <cuda_runtime.h>
#include <cuda_fp16.h>
#include <math.h>
#include <stdint.h>

// Problem constants
// N=16, C=128, T=128, V=25, K=3, H=8, OC=256, C/H=16, OC/H=32
// x: (16,128,128,25)  out: (16,256,128,25)

#define TV 3200          // T*V
#define CTV 409600       // C*T*V

// ---- scratch (device globals; allocation-free) ----
__device__ float d_BnA[24 * 625];
__device__ float d_bsum[256];
__device__ __align__(16) __half d_res_preh[16 * 256 * 3200];   // 26.2 MB
__device__ __align__(16) __half d_out_pre2h[16 * 8 * 128 * 800]; // 26.2 MB
__device__ __align__(16) __half d_G2h[8 * 896 * 400];   // fused weights fp16
__device__ __align__(16) __half d_xrh[16 * 8 * 128 * 400]; // x for main GEMM
__device__ __align__(16) __half d_xth[16 * 3200 * 128];    // x for res GEMM
__device__ __align__(16) __half d_rwh[256 * 128];          // res_w fp16
__device__ float d_ss[1024];
__device__ float d_rpart[800 * 256];             // res-path BN partials
__device__ float d_mpart[8 * 7 * 16 * 128 * 2];  // main-path BN partials

__device__ __forceinline__ void mma_f16(float c[4], const uint32_t a[4],
                                        const uint32_t b[2]) {
    asm volatile(
        "mma.sync.aligned.m16n8k16.row.col.f32.f16.f16.f32 "
        "{%0,%1,%2,%3},{%4,%5,%6,%7},{%8,%9},{%0,%1,%2,%3};"
        : "+f"(c[0]), "+f"(c[1]), "+f"(c[2]), "+f"(c[3])
        : "r"(a[0]), "r"(a[1]), "r"(a[2]), "r"(a[3]), "r"(b[0]), "r"(b[1]));
}

// ---------------------------------------------------------------------------
// Kernel 1: build BnA and summed bias.
// ---------------------------------------------------------------------------
__global__ void prep_kernel(const int* __restrict__ hop,
                            const float* __restrict__ emb,
                            const float* __restrict__ A,
                            const float* __restrict__ b_block) {
    int g = blockIdx.x;
    int w = threadIdx.x;
    if (g < 24) {
        if (w < 25) {
            const float* eg = emb + g * 12;
            const float* Ag = A + g * 625;
            float sb = 0.f, sa = 0.f;
            for (int v = 0; v < 25; ++v) {
                float bv = eg[hop[v * 25 + w]];
                float av = Ag[v * 25 + w];
                sb += bv * bv;
                sa += av * av;
            }
            float rb = 1.f / (sqrtf(sb) + 1e-4f);
            float ra = 1.f / (sqrtf(sa) + 1e-4f);
            for (int v = 0; v < 25; ++v) {
                float bv = eg[hop[v * 25 + w]];
                float av = Ag[v * 25 + w];
                d_BnA[g * 625 + v * 25 + w] = bv * rb + av * ra;
            }
        }
    } else {
        for (int oc = w; oc < 256; oc += 32)
            d_bsum[oc] = b_block[oc] + b_block[256 + oc] + b_block[512 + oc];
    }
}

// ---------------------------------------------------------------------------
// Kernel 1a: convert res_w -> fp16.
// ---------------------------------------------------------------------------
__global__ __launch_bounds__(256) void cvt_resw_kernel(
    const float* __restrict__ res_w) {
    int idx = (blockIdx.x * 256 + threadIdx.x) * 4;
    float4 v = *(const float4*)(res_w + idx);
    __half2* dst = (__half2*)(d_rwh + idx);
    dst[0] = __floats2half2_rn(v.x, v.y);
    dst[1] = __floats2half2_rn(v.z, v.w);
}

// ---------------------------------------------------------------------------
// Kernel 1b: G2h[h][o*25+w][c*25+v] = sum_k wg*BnA, fp16.
// ---------------------------------------------------------------------------
__global__ __launch_bounds__(256) void gbuild_kernel(
    const float* __restrict__ w_block) {
    int o = blockIdx.x;   // 0..32 (32 = row-pad block)
    int h = blockIdx.y;
    int tid = threadIdx.x;
    if (o == 32) {
        __half* dst = d_G2h + (h * 896 + 800) * 400;
        for (int idx = tid; idx < 96 * 400; idx += 256) dst[idx] = __half(0.f);
        return;
    }
    __shared__ float bna[3 * 625];
    __shared__ float wg3[48];
    for (int idx = tid; idx < 1875; idx += 256) {
        int k = idx / 625;
        bna[idx] = d_BnA[(k * 8 + h) * 625 + (idx - k * 625)];
    }
    if (tid < 48) {
        int k = tid / 16, c = tid & 15;
        wg3[tid] = w_block[(k * 8 + h) * 512 + o * 16 + c];
    }
    __syncthreads();
    __half* dst = d_G2h + (h * 896 + o * 25) * 400;
    for (int idx = tid; idx < 10000; idx += 256) {   // 25 w x 400 cv
        int w = idx / 400, cv = idx - w * 400;
        int c = cv / 25, v = cv - c * 25;
        int vw = v * 25 + w;
        float val = wg3[c] * bna[vw] + wg3[16 + c] * bna[625 + vw] +
                    wg3[32 + c] * bna[1250 + vw];
        dst[w * 400 + cv] = __float2half_rn(val);
    }
}

// ---------------------------------------------------------------------------
// Kernel 1c: d_xth[n][tv][h*16+c] (fp16) via smem tile transpose.
// Grid (16 n, 25 tiles, 8 h), one 16c x 128tv tile per CTA.
// ---------------------------------------------------------------------------
__global__ __launch_bounds__(256) void xth_kernel(const float* __restrict__ x) {
    __shared__ float xs[16 * 132];
    int n = blockIdx.x, tile = blockIdx.y, h = blockIdx.z;
    int tid = threadIdx.x;
    int tv0 = tile * 128;
    const float* xb = x + n * CTV + h * 16 * TV;
#pragma unroll
    for (int it = 0; it < 8; ++it) {
        int idx = tid + it * 256;            // 0..2047
        int cc = idx >> 7, j = idx & 127;
        xs[cc * 132 + j] = xb[cc * TV + tv0 + j];
    }
    __syncthreads();
#pragma unroll
    for (int it = 0; it < 4; ++it) {
        int idx = tid + it * 256;            // 0..1023
        int tvl = idx >> 3, ccp = idx & 7;
        __half2 hv = __floats2half2_rn(xs[(2 * ccp) * 132 + tvl],
                                       xs[(2 * ccp + 1) * 132 + tvl]);
        *(__half2*)(d_xth + (n * 3200 + tv0 + tvl) * 128 + h * 16 + ccp * 2) = hv;
    }
}

// ---------------------------------------------------------------------------
// Kernel 1d: d_xrh[n][h][t][c*25+v] (fp16) gather. Grid (16 n, 8 h, 8 tc).
// ---------------------------------------------------------------------------
__global__ __launch_bounds__(256) void xrh_kernel(const float* __restrict__ x) {
    int n = blockIdx.x, h = blockIdx.y, tc = blockIdx.z;
    int tid = threadIdx.x;
    const float* xb = x + n * CTV + h * 16 * TV + tc * 16 * 25;
    __half* dstr = d_xrh + ((n * 8 + h) * 128 + tc * 16) * 400;
#pragma unroll
    for (int it = 0; it < 25; ++it) {
        int idx = it * 256 + tid;                // 0..6399
        int t = idx / 400, j = idx - t * 400;
        int c = j / 25, v = j - c * 25;
        dstr[idx] = __float2half_rn(xb[c * TV + t * 25 + v]);
    }
}

// ---------------------------------------------------------------------------
// Kernel 2: res GEMM fp16 m16n8k16 (validated r8). fp16 output stores.
// ---------------------------------------------------------------------------
#define RES_SMEM_BYTES (34816 * 2 + 2048)

__global__ __launch_bounds__(256, 2) void res_gemm_tc(
    const float* __restrict__ res_b) {
    extern __shared__ __align__(16) char smem[];
    __half* As = (__half*)smem;                 // [o 128][136]
    __half* Bs = (__half*)(smem + 34816);       // [tv 128][136]
    float* part = (float*)(smem + 69632);

    const int tid = threadIdx.x;
    const int wid = tid >> 5, lane = tid & 31;
    const int gid = lane >> 2, tg = lane & 3;
    const int warp_m = wid >> 1;
    const int warp_n = wid & 1;
    const int tv0 = blockIdx.x * 128;
    const int o0 = blockIdx.y * 128;
    const int n = blockIdx.z;

    {
        const uint4* src = (const uint4*)(d_rwh + o0 * 128);
#pragma unroll
        for (int it = 0; it < 8; ++it) {
            int idx = tid + it * 256;            // 0..2047
            int row = idx >> 4, f = idx & 15;
            *(uint4*)(As + row * 136 + f * 8) = src[row * 16 + f];
        }
    }
    {
        const uint4* src = (const uint4*)(d_xth + (n * 3200 + tv0) * 128);
#pragma unroll
        for (int it = 0; it < 8; ++it) {
            int idx = tid + it * 256;
            int row = idx >> 4, f = idx & 15;
            *(uint4*)(Bs + row * 136 + f * 8) = src[row * 16 + f];
        }
    }
    __syncthreads();

    float c[2][8][4];
#pragma unroll
    for (int mt = 0; mt < 2; ++mt)
#pragma unroll
        for (int nt = 0; nt < 8; ++nt)
#pragma unroll
            for (int q = 0; q < 4; ++q) c[mt][nt][q] = 0.f;

    const uint32_t* Au = (const uint32_t*)As;
    const uint32_t* Bu = (const uint32_t*)Bs;
    const int arow = (warp_m * 32 + gid) * 68 + tg;
    const int brow = (warp_n * 64 + gid) * 68 + tg;

#pragma unroll
    for (int step = 0; step < 8; ++step) {
        const int k0 = step * 8;                 // words (16 halves per step)
        uint32_t a[2][4], b[8][2];
#pragma unroll
        for (int mt = 0; mt < 2; ++mt) {
            int base = arow + mt * 16 * 68 + k0;
            a[mt][0] = Au[base];
            a[mt][1] = Au[base + 8 * 68];
            a[mt][2] = Au[base + 4];
            a[mt][3] = Au[base + 8 * 68 + 4];
        }
#pragma unroll
        for (int nt = 0; nt < 8; ++nt) {
            int base = brow + nt * 8 * 68 + k0;
            b[nt][0] = Bu[base];
            b[nt][1] = Bu[base + 4];
        }
#pragma unroll
        for (int mt = 0; mt < 2; ++mt)
#pragma unroll
            for (int nt = 0; nt < 8; ++nt)
                mma_f16(c[mt][nt], a[mt], b[nt]);
    }

    const int colbase = tv0 + warp_n * 64 + 2 * tg;
#pragma unroll
    for (int mt = 0; mt < 2; ++mt) {
        int row0 = o0 + warp_m * 32 + mt * 16 + gid;
        float bias0 = res_b[row0];
        float bias1 = res_b[row0 + 8];
        float s0 = 0.f, q0 = 0.f, s1 = 0.f, q1 = 0.f;
        __half* dst0 = d_res_preh + (n * 256 + row0) * TV;
        __half* dst1 = dst0 + 8 * TV;
#pragma unroll
        for (int nt = 0; nt < 8; ++nt) {
            float v0 = c[mt][nt][0] + bias0;
            float v1 = c[mt][nt][1] + bias0;
            float v2 = c[mt][nt][2] + bias1;
            float v3 = c[mt][nt][3] + bias1;
            s0 += v0 + v1;  q0 += v0 * v0 + v1 * v1;
            s1 += v2 + v3;  q1 += v2 * v2 + v3 * v3;
            int col = colbase + nt * 8;
            *(__half2*)(dst0 + col) = __floats2half2_rn(v0, v1);
            *(__half2*)(dst1 + col) = __floats2half2_rn(v2, v3);
        }
#pragma unroll
        for (int off = 1; off <= 2; off <<= 1) {
            s0 += __shfl_xor_sync(0xFFFFFFFFu, s0, off);
            q0 += __shfl_xor_sync(0xFFFFFFFFu, q0, off);
            s1 += __shfl_xor_sync(0xFFFFFFFFu, s1, off);
            q1 += __shfl_xor_sync(0xFFFFFFFFu, q1, off);
        }
        if (tg == 0) {
            int r = warp_m * 32 + mt * 16 + gid;
            part[(warp_n * 128 + r) * 2] = s0;
            part[(warp_n * 128 + r) * 2 + 1] = q0;
            part[(warp_n * 128 + r + 8) * 2] = s1;
            part[(warp_n * 128 + r + 8) * 2 + 1] = q1;
        }
    }
    __syncthreads();
    if (tid < 128) {
        float s = part[tid * 2] + part[(128 + tid) * 2];
        float q = part[tid * 2 + 1] + part[(128 + tid) * 2 + 1];
        int blk = (n * 2 + blockIdx.y) * 25 + blockIdx.x;
        d_rpart[blk * 256 + tid * 2] = s;
        d_rpart[blk * 256 + tid * 2 + 1] = q;
    }
}

// ---------------------------------------------------------------------------
// Kernel 3: main fused GEMM fp16 (validated r8). fp16 output stores.
// ---------------------------------------------------------------------------
#define MAIN_SMEM_BYTES (22528 * 2 + 2048)

__global__ __launch_bounds__(256, 2) void main_gemm_tc() {
    extern __shared__ __align__(16) char smem[];
    __half* As = (__half*)smem;                 // [128 rows][88]
    __half* Bs = (__half*)(smem + 22528);       // [128 t][88]
    float* part = (float*)(smem + 45056);

    const int tid = threadIdx.x;
    const int wid = tid >> 5, lane = tid & 31;
    const int gid = lane >> 2, tg = lane & 3;
    const int warp_m = wid >> 1;
    const int warp_n = wid & 1;
    const int n = blockIdx.x;
    const int mb = blockIdx.y;
    const int m0 = mb * 128;
    const int h = blockIdx.z;

    float c[2][8][4];
#pragma unroll
    for (int mt = 0; mt < 2; ++mt)
#pragma unroll
        for (int nt = 0; nt < 8; ++nt)
#pragma unroll
            for (int q = 0; q < 4; ++q) c[mt][nt][q] = 0.f;

    const uint32_t* Au = (const uint32_t*)As;
    const uint32_t* Bu = (const uint32_t*)Bs;
    const int arow = (warp_m * 32 + gid) * 44 + tg;
    const int brow = (warp_n * 64 + gid) * 44 + tg;
    const __half* gbase = d_G2h + (h * 896 + m0) * 400;
    const __half* xbase = d_xrh + (n * 8 + h) * 128 * 400;

    for (int q = 0; q < 5; ++q) {
        const int kc0 = q * 80;                  // halves
        __syncthreads();
#pragma unroll
        for (int it = 0; it < 5; ++it) {
            int idx = tid + it * 256;            // 0..1279
            int row = idx / 10, f = idx - row * 10;
            *(uint4*)(As + row * 88 + f * 8) =
                *(const uint4*)(gbase + row * 400 + kc0 + f * 8);
        }
#pragma unroll
        for (int it = 0; it < 5; ++it) {
            int idx = tid + it * 256;
            int row = idx / 10, f = idx - row * 10;
            *(uint4*)(Bs + row * 88 + f * 8) =
                *(const uint4*)(xbase + row * 400 + kc0 + f * 8);
        }
        __syncthreads();

#pragma unroll
        for (int step = 0; step < 5; ++step) {
            const int k0 = step * 8;             // words
            uint32_t a[2][4], b[8][2];
#pragma unroll
            for (int mt = 0; mt < 2; ++mt) {
                int base = arow + mt * 16 * 44 + k0;
                a[mt][0] = Au[base];
                a[mt][1] = Au[base + 8 * 44];
                a[mt][2] = Au[base + 4];
                a[mt][3] = Au[base + 8 * 44 + 4];
            }
#pragma unroll
            for (int nt = 0; nt < 8; ++nt) {
                int base = brow + nt * 8 * 44 + k0;
                b[nt][0] = Bu[base];
                b[nt][1] = Bu[base + 4];
            }
#pragma unroll
            for (int mt = 0; mt < 2; ++mt)
#pragma unroll
                for (int nt = 0; nt < 8; ++nt)
                    mma_f16(c[mt][nt], a[mt], b[nt]);
        }
    }

    // Epilogue: bias, store fp16 to [n][h][t][ow], BN partials.
    __half* obase = d_out_pre2h + (n * 8 + h) * 128 * 800;
#pragma unroll
    for (int mt = 0; mt < 2; ++mt) {
        int r0 = m0 + warp_m * 32 + mt * 16 + gid;
        int o0 = r0 / 25, o1 = (r0 + 8) / 25;
        float bias0 = (r0 < 800) ? d_bsum[h * 32 + o0] : 0.f;
        float bias1 = (r0 + 8 < 800) ? d_bsum[h * 32 + o1] : 0.f;
        float s0 = 0.f, q0 = 0.f, s1 = 0.f, q1 = 0.f;
        int colbase = warp_n * 64 + 2 * tg;
#pragma unroll
        for (int nt = 0; nt < 8; ++nt) {
            float v0 = c[mt][nt][0] + bias0;
            float v1 = c[mt][nt][1] + bias0;
            float v2 = c[mt][nt][2] + bias1;
            float v3 = c[mt][nt][3] + bias1;
            s0 += v0 + v1;  q0 += v0 * v0 + v1 * v1;
            s1 += v2 + v3;  q1 += v2 * v2 + v3 * v3;
            int col = colbase + nt * 8;
            if (r0 < 800) {
                obase[col * 800 + r0] = __float2half_rn(v0);
                obase[(col + 1) * 800 + r0] = __float2half_rn(v1);
            }
            if (r0 + 8 < 800) {
                obase[col * 800 + r0 + 8] = __float2half_rn(v2);
                obase[(col + 1) * 800 + r0 + 8] = __float2half_rn(v3);
            }
        }
#pragma unroll
        for (int off = 1; off <= 2; off <<= 1) {
            s0 += __shfl_xor_sync(0xFFFFFFFFu, s0, off);
            q0 += __shfl_xor_sync(0xFFFFFFFFu, q0, off);
            s1 += __shfl_xor_sync(0xFFFFFFFFu, s1, off);
            q1 += __shfl_xor_sync(0xFFFFFFFFu, q1, off);
        }
        if (tg == 0) {
            int r = warp_m * 32 + mt * 16 + gid;
            part[(warp_n * 128 + r) * 2] = s0;
            part[(warp_n * 128 + r) * 2 + 1] = q0;
            part[(warp_n * 128 + r + 8) * 2] = s1;
            part[(warp_n * 128 + r + 8) * 2 + 1] = q1;
        }
    }
    __syncthreads();
    if (tid < 128) {
        float s = part[tid * 2] + part[(128 + tid) * 2];
        float q = part[tid * 2 + 1] + part[(128 + tid) * 2 + 1];
        int blk = (h * 7 + mb) * 16 + n;
        d_mpart[(blk * 128 + tid) * 2] = s;
        d_mpart[(blk * 128 + tid) * 2 + 1] = q;
    }
}

// ---------------------------------------------------------------------------
// Kernel 4a: out-path BN stats from GEMM partials.
// ---------------------------------------------------------------------------
__global__ __launch_bounds__(128) void stats_out_kernel(
    const float* __restrict__ bn_gamma, const float* __restrict__ bn_beta) {
    __shared__ float ssum[128];
    __shared__ float ssq[128];
    int ch = blockIdx.x;
    int h = ch >> 5, o = ch & 31;
    int tid = threadIdx.x;

    float s = 0.f, q = 0.f;
    for (int e = tid; e < 400; e += 128) {
        int w = e >> 4, nn = e & 15;
        int grow = o * 25 + w;
        int mb = grow >> 7, lr = grow & 127;
        int blk = (h * 7 + mb) * 16 + nn;
        s += d_mpart[(blk * 128 + lr) * 2];
        q += d_mpart[(blk * 128 + lr) * 2 + 1];
    }
    ssum[tid] = s;
    ssq[tid] = q;
    __syncthreads();
    for (int st = 64; st > 0; st >>= 1) {
        if (tid < st) {
            ssum[tid] += ssum[tid + st];
            ssq[tid] += ssq[tid + st];
        }
        __syncthreads();
    }
    if (tid == 0) {
        const float inv = 1.f / 51200.f;
        float mean = ssum[0] * inv;
        float var = ssq[0] * inv - mean * mean;
        float sc = bn_gamma[ch] * rsqrtf(var + 1e-5f);
        d_ss[ch] = sc;
        d_ss[256 + ch] = bn_beta[ch] - mean * sc;
    }
}

// ---------------------------------------------------------------------------
// Kernel 4b: res-path BN stats from GEMM partials.
// ---------------------------------------------------------------------------
__global__ __launch_bounds__(128) void stats_res_kernel(
    const float* __restrict__ res_bn_gamma, const float* __restrict__ res_bn_beta) {
    __shared__ float ssum[128];
    __shared__ float ssq[128];
    int ch = blockIdx.x;
    int ob = ch >> 7, row = ch & 127;
    int tid = threadIdx.x;

    float s = 0.f, q = 0.f;
    for (int e = tid; e < 400; e += 128) {
        int nn = e / 25, tvb = e - nn * 25;
        int blk = (nn * 2 + ob) * 25 + tvb;
        s += d_rpart[blk * 256 + row * 2];
        q += d_rpart[blk * 256 + row * 2 + 1];
    }
    ssum[tid] = s;
    ssq[tid] = q;
    __syncthreads();
    for (int st = 64; st > 0; st >>= 1) {
        if (tid < st) {
            ssum[tid] += ssum[tid + st];
            ssq[tid] += ssq[tid + st];
        }
        __syncthreads();
    }
    if (tid == 0) {
        const float inv = 1.f / 51200.f;
        float mean = ssum[0] * inv;
        float var = ssq[0] * inv - mean * mean;
        float sc = res_bn_gamma[ch] * rsqrtf(var + 1e-5f);
        d_ss[512 + ch] = sc;
        d_ss[768 + ch] = res_bn_beta[ch] - mean * sc;
    }
}

// ---------------------------------------------------------------------------
// Kernel 5: out = relu(BN(out_pre2h) + BN(res_preh)). One block per (n,t).
// ---------------------------------------------------------------------------
__global__ __launch_bounds__(256) void final_kernel(float* __restrict__ out) {
    int b = blockIdx.x;
    int n = b >> 7, t = b & 127;
    int tid = threadIdx.x;
    const __half* p2 = d_out_pre2h + (n * 8) * 128 * 800 + t * 800;
#pragma unroll
    for (int it = 0; it < 25; ++it) {
        int idx = it * 256 + tid;          // 0..6399
        int ch = idx / 25, w = idx - ch * 25;
        int h = ch >> 5, o = ch & 31;
        float op = __half2float(p2[h * 128 * 800 + o * 25 + w]);
        float rp = __half2float(d_res_preh[((n * 256 + ch) * 128 + t) * 25 + w]);
        float so = d_ss[ch], ho = d_ss[256 + ch];
        float sr = d_ss[512 + ch], hr = d_ss[768 + ch];
        float r = fmaxf(fmaf(op, so, ho) + fmaf(rp, sr, hr), 0.f);
        out[((n * 256 + ch) * 128 + t) * 25 + w] = r;
    }
}

// ---------------------------------------------------------------------------
extern "C" void kernel_launch(void* const* d_in, const int* in_sizes, int n_in,
                              void* d_out, int out_size) {
    const float* x            = (const float*)d_in[0];
    const int*   hop          = (const int*)d_in[1];
    const float* emb          = (const float*)d_in[2];
    const float* A            = (const float*)d_in[3];
    const float* w_block      = (const float*)d_in[4];
    const float* b_block      = (const float*)d_in[5];
    const float* bn_gamma     = (const float*)d_in[6];
    const float* bn_beta      = (const float*)d_in[7];
    const float* res_w        = (const float*)d_in[8];
    const float* res_b        = (const float*)d_in[9];
    const float* res_bn_gamma = (const float*)d_in[10];
    const float* res_bn_beta  = (const float*)d_in[11];
    float* out = (float*)d_out;

    cudaFuncSetAttribute(res_gemm_tc, cudaFuncAttributeMaxDynamicSharedMemorySize,
                         RES_SMEM_BYTES);
    cudaFuncSetAttribute(main_gemm_tc, cudaFuncAttributeMaxDynamicSharedMemorySize,
                         MAIN_SMEM_BYTES);

    prep_kernel<<<25, 32>>>(hop, emb, A, b_block);
    cvt_resw_kernel<<<32, 256>>>(res_w);
    gbuild_kernel<<<dim3(33, 8), 256>>>(w_block);
    xth_kernel<<<dim3(16, 25, 8), 256>>>(x);
    xrh_kernel<<<dim3(16, 8, 8), 256>>>(x);
    res_gemm_tc<<<dim3(25, 2, 16), 256, RES_SMEM_BYTES>>>(res_b);
    main_gemm_tc<<<dim3(16, 7, 8), 256, MAIN_SMEM_BYTES>>>();
    stats_out_kernel<<<256, 128>>>(bn_gamma, bn_beta);
    stats_res_kernel<<<256, 128>>>(res_bn_gamma, res_bn_beta);
    final_kernel<<<2048, 256>>>(out);
}

// round 10
// speedup vs baseline: 1.9437x; 1.0422x over previous
#include <cuda_runtime.h>
#include <cuda_fp16.h>
#include <math.h>
#include <stdint.h>

// Problem constants
// N=16, C=128, T=128, V=25, K=3, H=8, OC=256, C/H=16, OC/H=32
// x: (16,128,128,25)  out: (16,256,128,25)

#define TV 3200          // T*V
#define CTV 409600       // C*T*V

// ---- scratch (device globals; allocation-free) ----
__device__ float d_BnA[24 * 625];
__device__ float d_bsum[256];
__device__ __align__(16) __half d_res_preh[16 * 256 * 3200];   // 26.2 MB
__device__ __align__(16) __half d_out_pre2h[16 * 8 * 128 * 800]; // 26.2 MB
__device__ __align__(16) __half d_G2h[8 * 896 * 400];   // fused weights fp16
__device__ __align__(16) __half d_xrh[16 * 8 * 128 * 400]; // x for main GEMM
__device__ __align__(16) __half d_xth[16 * 3200 * 128];    // x for res GEMM
__device__ __align__(16) __half d_rwh[256 * 128];          // res_w fp16
__device__ float d_ss[1024];
__device__ float d_rpart[800 * 256];             // res-path BN partials
__device__ float d_mpart[8 * 7 * 16 * 128 * 2];  // main-path BN partials

__device__ __forceinline__ void mma_f16(float c[4], const uint32_t a[4],
                                        const uint32_t b[2]) {
    asm volatile(
        "mma.sync.aligned.m16n8k16.row.col.f32.f16.f16.f32 "
        "{%0,%1,%2,%3},{%4,%5,%6,%7},{%8,%9},{%0,%1,%2,%3};"
        : "+f"(c[0]), "+f"(c[1]), "+f"(c[2]), "+f"(c[3])
        : "r"(a[0]), "r"(a[1]), "r"(a[2]), "r"(a[3]), "r"(b[0]), "r"(b[1]));
}

// ---------------------------------------------------------------------------
// Kernel 1: build BnA and summed bias.
// ---------------------------------------------------------------------------
__global__ void prep_kernel(const int* __restrict__ hop,
                            const float* __restrict__ emb,
                            const float* __restrict__ A,
                            const float* __restrict__ b_block) {
    int g = blockIdx.x;
    int w = threadIdx.x;
    if (g < 24) {
        if (w < 25) {
            const float* eg = emb + g * 12;
            const float* Ag = A + g * 625;
            float sb = 0.f, sa = 0.f;
            for (int v = 0; v < 25; ++v) {
                float bv = eg[hop[v * 25 + w]];
                float av = Ag[v * 25 + w];
                sb += bv * bv;
                sa += av * av;
            }
            float rb = 1.f / (sqrtf(sb) + 1e-4f);
            float ra = 1.f / (sqrtf(sa) + 1e-4f);
            for (int v = 0; v < 25; ++v) {
                float bv = eg[hop[v * 25 + w]];
                float av = Ag[v * 25 + w];
                d_BnA[g * 625 + v * 25 + w] = bv * rb + av * ra;
            }
        }
    } else {
        for (int oc = w; oc < 256; oc += 32)
            d_bsum[oc] = b_block[oc] + b_block[256 + oc] + b_block[512 + oc];
    }
}

// ---------------------------------------------------------------------------
// Kernel 1a: convert res_w -> fp16.
// ---------------------------------------------------------------------------
__global__ __launch_bounds__(256) void cvt_resw_kernel(
    const float* __restrict__ res_w) {
    int idx = (blockIdx.x * 256 + threadIdx.x) * 4;
    float4 v = *(const float4*)(res_w + idx);
    __half2* dst = (__half2*)(d_rwh + idx);
    dst[0] = __floats2half2_rn(v.x, v.y);
    dst[1] = __floats2half2_rn(v.z, v.w);
}

// ---------------------------------------------------------------------------
// Kernel 1b: G2h[h][o*25+w][c*25+v] = sum_k wg*BnA, fp16.
// ---------------------------------------------------------------------------
__global__ __launch_bounds__(256) void gbuild_kernel(
    const float* __restrict__ w_block) {
    int o = blockIdx.x;   // 0..32 (32 = row-pad block)
    int h = blockIdx.y;
    int tid = threadIdx.x;
    if (o == 32) {
        __half* dst = d_G2h + (h * 896 + 800) * 400;
        for (int idx = tid; idx < 96 * 400; idx += 256) dst[idx] = __half(0.f);
        return;
    }
    __shared__ float bna[3 * 625];
    __shared__ float wg3[48];
    for (int idx = tid; idx < 1875; idx += 256) {
        int k = idx / 625;
        bna[idx] = d_BnA[(k * 8 + h) * 625 + (idx - k * 625)];
    }
    if (tid < 48) {
        int k = tid / 16, c = tid & 15;
        wg3[tid] = w_block[(k * 8 + h) * 512 + o * 16 + c];
    }
    __syncthreads();
    __half* dst = d_G2h + (h * 896 + o * 25) * 400;
    for (int idx = tid; idx < 10000; idx += 256) {   // 25 w x 400 cv
        int w = idx / 400, cv = idx - w * 400;
        int c = cv / 25, v = cv - c * 25;
        int vw = v * 25 + w;
        float val = wg3[c] * bna[vw] + wg3[16 + c] * bna[625 + vw] +
                    wg3[32 + c] * bna[1250 + vw];
        dst[w * 400 + cv] = __float2half_rn(val);
    }
}

// ---------------------------------------------------------------------------
// Kernel 1c: unified x prep. Grid (16 n, 8 h, 8 tc). Each CTA stages its
// 16c x 400tv slab once, emits d_xth (uint4 stores) and d_xrh (gather).
// ---------------------------------------------------------------------------
__global__ __launch_bounds__(256) void xprep_kernel(const float* __restrict__ x) {
    __shared__ __align__(16) float xs[16 * 404];
    int n = blockIdx.x, h = blockIdx.y, tc = blockIdx.z;
    int tid = threadIdx.x;
    const float* xb = x + n * CTV + h * 16 * TV + tc * 400;

    // Load slab: 16 rows x 400 floats = 1600 float4
#pragma unroll
    for (int it = 0; it < 7; ++it) {
        int idx = tid + it * 256;
        if (idx < 1600) {
            int c = idx / 100, f = idx - c * 100;
            *(float4*)(xs + c * 404 + f * 4) = *(const float4*)(xb + c * TV + f * 4);
        }
    }
    __syncthreads();

    // d_xth[n][tv][h*16+c]: 400 tv x 2 uint4 (8 halves each)
#pragma unroll
    for (int it = 0; it < 4; ++it) {
        int id = tid + it * 256;
        if (id < 800) {
            int tv = id >> 1, q = id & 1;
            __half hbuf[8];
#pragma unroll
            for (int cc = 0; cc < 8; ++cc)
                hbuf[cc] = __float2half_rn(xs[(q * 8 + cc) * 404 + tv]);
            *(uint4*)(d_xth + (n * 3200 + tc * 400 + tv) * 128 + h * 16 + q * 8) =
                *(uint4*)hbuf;
        }
    }
    // d_xrh[n][h][t][c*25+v]: 16 t x 400
    __half* dstr = d_xrh + ((n * 8 + h) * 128 + tc * 16) * 400;
#pragma unroll
    for (int it = 0; it < 25; ++it) {
        int idx = it * 256 + tid;                // 0..6399
        int t = idx / 400, j = idx - t * 400;
        int c = j / 25, v = j - c * 25;
        dstr[idx] = __float2half_rn(xs[c * 404 + t * 25 + v]);
    }
}

// ---------------------------------------------------------------------------
// Kernel 2: res GEMM fp16 m16n8k16 (validated r8/r9). fp16 output stores.
// ---------------------------------------------------------------------------
#define RES_SMEM_BYTES (34816 * 2 + 2048)

__global__ __launch_bounds__(256, 2) void res_gemm_tc(
    const float* __restrict__ res_b) {
    extern __shared__ __align__(16) char smem[];
    __half* As = (__half*)smem;                 // [o 128][136]
    __half* Bs = (__half*)(smem + 34816);       // [tv 128][136]
    float* part = (float*)(smem + 69632);

    const int tid = threadIdx.x;
    const int wid = tid >> 5, lane = tid & 31;
    const int gid = lane >> 2, tg = lane & 3;
    const int warp_m = wid >> 1;
    const int warp_n = wid & 1;
    const int tv0 = blockIdx.x * 128;
    const int o0 = blockIdx.y * 128;
    const int n = blockIdx.z;

    {
        const uint4* src = (const uint4*)(d_rwh + o0 * 128);
#pragma unroll
        for (int it = 0; it < 8; ++it) {
            int idx = tid + it * 256;            // 0..2047
            int row = idx >> 4, f = idx & 15;
            *(uint4*)(As + row * 136 + f * 8) = src[row * 16 + f];
        }
    }
    {
        const uint4* src = (const uint4*)(d_xth + (n * 3200 + tv0) * 128);
#pragma unroll
        for (int it = 0; it < 8; ++it) {
            int idx = tid + it * 256;
            int row = idx >> 4, f = idx & 15;
            *(uint4*)(Bs + row * 136 + f * 8) = src[row * 16 + f];
        }
    }
    __syncthreads();

    float c[2][8][4];
#pragma unroll
    for (int mt = 0; mt < 2; ++mt)
#pragma unroll
        for (int nt = 0; nt < 8; ++nt)
#pragma unroll
            for (int q = 0; q < 4; ++q) c[mt][nt][q] = 0.f;

    const uint32_t* Au = (const uint32_t*)As;
    const uint32_t* Bu = (const uint32_t*)Bs;
    const int arow = (warp_m * 32 + gid) * 68 + tg;
    const int brow = (warp_n * 64 + gid) * 68 + tg;

#pragma unroll
    for (int step = 0; step < 8; ++step) {
        const int k0 = step * 8;                 // words (16 halves per step)
        uint32_t a[2][4], b[8][2];
#pragma unroll
        for (int mt = 0; mt < 2; ++mt) {
            int base = arow + mt * 16 * 68 + k0;
            a[mt][0] = Au[base];
            a[mt][1] = Au[base + 8 * 68];
            a[mt][2] = Au[base + 4];
            a[mt][3] = Au[base + 8 * 68 + 4];
        }
#pragma unroll
        for (int nt = 0; nt < 8; ++nt) {
            int base = brow + nt * 8 * 68 + k0;
            b[nt][0] = Bu[base];
            b[nt][1] = Bu[base + 4];
        }
#pragma unroll
        for (int mt = 0; mt < 2; ++mt)
#pragma unroll
            for (int nt = 0; nt < 8; ++nt)
                mma_f16(c[mt][nt], a[mt], b[nt]);
    }

    const int colbase = tv0 + warp_n * 64 + 2 * tg;
#pragma unroll
    for (int mt = 0; mt < 2; ++mt) {
        int row0 = o0 + warp_m * 32 + mt * 16 + gid;
        float bias0 = res_b[row0];
        float bias1 = res_b[row0 + 8];
        float s0 = 0.f, q0 = 0.f, s1 = 0.f, q1 = 0.f;
        __half* dst0 = d_res_preh + (n * 256 + row0) * TV;
        __half* dst1 = dst0 + 8 * TV;
#pragma unroll
        for (int nt = 0; nt < 8; ++nt) {
            float v0 = c[mt][nt][0] + bias0;
            float v1 = c[mt][nt][1] + bias0;
            float v2 = c[mt][nt][2] + bias1;
            float v3 = c[mt][nt][3] + bias1;
            s0 += v0 + v1;  q0 += v0 * v0 + v1 * v1;
            s1 += v2 + v3;  q1 += v2 * v2 + v3 * v3;
            int col = colbase + nt * 8;
            *(__half2*)(dst0 + col) = __floats2half2_rn(v0, v1);
            *(__half2*)(dst1 + col) = __floats2half2_rn(v2, v3);
        }
#pragma unroll
        for (int off = 1; off <= 2; off <<= 1) {
            s0 += __shfl_xor_sync(0xFFFFFFFFu, s0, off);
            q0 += __shfl_xor_sync(0xFFFFFFFFu, q0, off);
            s1 += __shfl_xor_sync(0xFFFFFFFFu, s1, off);
            q1 += __shfl_xor_sync(0xFFFFFFFFu, q1, off);
        }
        if (tg == 0) {
            int r = warp_m * 32 + mt * 16 + gid;
            part[(warp_n * 128 + r) * 2] = s0;
            part[(warp_n * 128 + r) * 2 + 1] = q0;
            part[(warp_n * 128 + r + 8) * 2] = s1;
            part[(warp_n * 128 + r + 8) * 2 + 1] = q1;
        }
    }
    __syncthreads();
    if (tid < 128) {
        float s = part[tid * 2] + part[(128 + tid) * 2];
        float q = part[tid * 2 + 1] + part[(128 + tid) * 2 + 1];
        int blk = (n * 2 + blockIdx.y) * 25 + blockIdx.x;
        d_rpart[blk * 256 + tid * 2] = s;
        d_rpart[blk * 256 + tid * 2 + 1] = q;
    }
}

// ---------------------------------------------------------------------------
// Kernel 3: main fused GEMM fp16 (validated r8/r9). fp16 output stores.
// ---------------------------------------------------------------------------
#define MAIN_SMEM_BYTES (22528 * 2 + 2048)

__global__ __launch_bounds__(256, 2) void main_gemm_tc() {
    extern __shared__ __align__(16) char smem[];
    __half* As = (__half*)smem;                 // [128 rows][88]
    __half* Bs = (__half*)(smem + 22528);       // [128 t][88]
    float* part = (float*)(smem + 45056);

    const int tid = threadIdx.x;
    const int wid = tid >> 5, lane = tid & 31;
    const int gid = lane >> 2, tg = lane & 3;
    const int warp_m = wid >> 1;
    const int warp_n = wid & 1;
    const int n = blockIdx.x;
    const int mb = blockIdx.y;
    const int m0 = mb * 128;
    const int h = blockIdx.z;

    float c[2][8][4];
#pragma unroll
    for (int mt = 0; mt < 2; ++mt)
#pragma unroll
        for (int nt = 0; nt < 8; ++nt)
#pragma unroll
            for (int q = 0; q < 4; ++q) c[mt][nt][q] = 0.f;

    const uint32_t* Au = (const uint32_t*)As;
    const uint32_t* Bu = (const uint32_t*)Bs;
    const int arow = (warp_m * 32 + gid) * 44 + tg;
    const int brow = (warp_n * 64 + gid) * 44 + tg;
    const __half* gbase = d_G2h + (h * 896 + m0) * 400;
    const __half* xbase = d_xrh + (n * 8 + h) * 128 * 400;

    for (int q = 0; q < 5; ++q) {
        const int kc0 = q * 80;                  // halves
        __syncthreads();
#pragma unroll
        for (int it = 0; it < 5; ++it) {
            int idx = tid + it * 256;            // 0..1279
            int row = idx / 10, f = idx - row * 10;
            *(uint4*)(As + row * 88 + f * 8) =
                *(const uint4*)(gbase + row * 400 + kc0 + f * 8);
        }
#pragma unroll
        for (int it = 0; it < 5; ++it) {
            int idx = tid + it * 256;
            int row = idx / 10, f = idx - row * 10;
            *(uint4*)(Bs + row * 88 + f * 8) =
                *(const uint4*)(xbase + row * 400 + kc0 + f * 8);
        }
        __syncthreads();

#pragma unroll
        for (int step = 0; step < 5; ++step) {
            const int k0 = step * 8;             // words
            uint32_t a[2][4], b[8][2];
#pragma unroll
            for (int mt = 0; mt < 2; ++mt) {
                int base = arow + mt * 16 * 44 + k0;
                a[mt][0] = Au[base];
                a[mt][1] = Au[base + 8 * 44];
                a[mt][2] = Au[base + 4];
                a[mt][3] = Au[base + 8 * 44 + 4];
            }
#pragma unroll
            for (int nt = 0; nt < 8; ++nt) {
                int base = brow + nt * 8 * 44 + k0;
                b[nt][0] = Bu[base];
                b[nt][1] = Bu[base + 4];
            }
#pragma unroll
            for (int mt = 0; mt < 2; ++mt)
#pragma unroll
                for (int nt = 0; nt < 8; ++nt)
                    mma_f16(c[mt][nt], a[mt], b[nt]);
        }
    }

    // Epilogue: bias, store fp16 to [n][h][t][ow], BN partials.
    __half* obase = d_out_pre2h + (n * 8 + h) * 128 * 800;
#pragma unroll
    for (int mt = 0; mt < 2; ++mt) {
        int r0 = m0 + warp_m * 32 + mt * 16 + gid;
        int o0 = r0 / 25, o1 = (r0 + 8) / 25;
        float bias0 = (r0 < 800) ? d_bsum[h * 32 + o0] : 0.f;
        float bias1 = (r0 + 8 < 800) ? d_bsum[h * 32 + o1] : 0.f;
        float s0 = 0.f, q0 = 0.f, s1 = 0.f, q1 = 0.f;
        int colbase = warp_n * 64 + 2 * tg;
#pragma unroll
        for (int nt = 0; nt < 8; ++nt) {
            float v0 = c[mt][nt][0] + bias0;
            float v1 = c[mt][nt][1] + bias0;
            float v2 = c[mt][nt][2] + bias1;
            float v3 = c[mt][nt][3] + bias1;
            s0 += v0 + v1;  q0 += v0 * v0 + v1 * v1;
            s1 += v2 + v3;  q1 += v2 * v2 + v3 * v3;
            int col = colbase + nt * 8;
            if (r0 < 800) {
                obase[col * 800 + r0] = __float2half_rn(v0);
                obase[(col + 1) * 800 + r0] = __float2half_rn(v1);
            }
            if (r0 + 8 < 800) {
                obase[col * 800 + r0 + 8] = __float2half_rn(v2);
                obase[(col + 1) * 800 + r0 + 8] = __float2half_rn(v3);
            }
        }
#pragma unroll
        for (int off = 1; off <= 2; off <<= 1) {
            s0 += __shfl_xor_sync(0xFFFFFFFFu, s0, off);
            q0 += __shfl_xor_sync(0xFFFFFFFFu, q0, off);
            s1 += __shfl_xor_sync(0xFFFFFFFFu, s1, off);
            q1 += __shfl_xor_sync(0xFFFFFFFFu, q1, off);
        }
        if (tg == 0) {
            int r = warp_m * 32 + mt * 16 + gid;
            part[(warp_n * 128 + r) * 2] = s0;
            part[(warp_n * 128 + r) * 2 + 1] = q0;
            part[(warp_n * 128 + r + 8) * 2] = s1;
            part[(warp_n * 128 + r + 8) * 2 + 1] = q1;
        }
    }
    __syncthreads();
    if (tid < 128) {
        float s = part[tid * 2] + part[(128 + tid) * 2];
        float q = part[tid * 2 + 1] + part[(128 + tid) * 2 + 1];
        int blk = (h * 7 + mb) * 16 + n;
        d_mpart[(blk * 128 + tid) * 2] = s;
        d_mpart[(blk * 128 + tid) * 2 + 1] = q;
    }
}

// ---------------------------------------------------------------------------
// Kernel 4: merged BN stats (both paths). Grid 512: which = blk>>8.
// ---------------------------------------------------------------------------
__global__ __launch_bounds__(128) void stats_kernel(
    const float* __restrict__ bn_gamma, const float* __restrict__ bn_beta,
    const float* __restrict__ res_bn_gamma, const float* __restrict__ res_bn_beta) {
    __shared__ float ssum[128];
    __shared__ float ssq[128];
    int which = blockIdx.x >> 8;
    int ch = blockIdx.x & 255;
    int tid = threadIdx.x;

    float s = 0.f, q = 0.f;
    if (which == 0) {
        int h = ch >> 5, o = ch & 31;
        for (int e = tid; e < 400; e += 128) {
            int w = e >> 4, nn = e & 15;
            int grow = o * 25 + w;
            int mb = grow >> 7, lr = grow & 127;
            int blk = (h * 7 + mb) * 16 + nn;
            s += d_mpart[(blk * 128 + lr) * 2];
            q += d_mpart[(blk * 128 + lr) * 2 + 1];
        }
    } else {
        int ob = ch >> 7, row = ch & 127;
        for (int e = tid; e < 400; e += 128) {
            int nn = e / 25, tvb = e - nn * 25;
            int blk = (nn * 2 + ob) * 25 + tvb;
            s += d_rpart[blk * 256 + row * 2];
            q += d_rpart[blk * 256 + row * 2 + 1];
        }
    }
    ssum[tid] = s;
    ssq[tid] = q;
    __syncthreads();
    for (int st = 64; st > 0; st >>= 1) {
        if (tid < st) {
            ssum[tid] += ssum[tid + st];
            ssq[tid] += ssq[tid + st];
        }
        __syncthreads();
    }
    if (tid == 0) {
        const float inv = 1.f / 51200.f;
        float mean = ssum[0] * inv;
        float var = ssq[0] * inv - mean * mean;
        float g = which ? res_bn_gamma[ch] : bn_gamma[ch];
        float b = which ? res_bn_beta[ch] : bn_beta[ch];
        float sc = g * rsqrtf(var + 1e-5f);
        d_ss[which * 512 + ch] = sc;
        d_ss[which * 512 + 256 + ch] = b - mean * sc;
    }
}

// ---------------------------------------------------------------------------
// Kernel 5: out = relu(BN(out_pre2h) + BN(res_preh)). One block per (n,t).
// ---------------------------------------------------------------------------
__global__ __launch_bounds__(256) void final_kernel(float* __restrict__ out) {
    int b = blockIdx.x;
    int n = b >> 7, t = b & 127;
    int tid = threadIdx.x;
    const __half* p2 = d_out_pre2h + (n * 8) * 128 * 800 + t * 800;
#pragma unroll
    for (int it = 0; it < 25; ++it) {
        int idx = it * 256 + tid;          // 0..6399
        int ch = idx / 25, w = idx - ch * 25;
        int h = ch >> 5, o = ch & 31;
        float op = __half2float(p2[h * 128 * 800 + o * 25 + w]);
        float rp = __half2float(d_res_preh[((n * 256 + ch) * 128 + t) * 25 + w]);
        float so = d_ss[ch], ho = d_ss[256 + ch];
        float sr = d_ss[512 + ch], hr = d_ss[768 + ch];
        float r = fmaxf(fmaf(op, so, ho) + fmaf(rp, sr, hr), 0.f);
        out[((n * 256 + ch) * 128 + t) * 25 + w] = r;
    }
}

// ---------------------------------------------------------------------------
extern "C" void kernel_launch(void* const* d_in, const int* in_sizes, int n_in,
                              void* d_out, int out_size) {
    const float* x            = (const float*)d_in[0];
    const int*   hop          = (const int*)d_in[1];
    const float* emb          = (const float*)d_in[2];
    const float* A            = (const float*)d_in[3];
    const float* w_block      = (const float*)d_in[4];
    const float* b_block      = (const float*)d_in[5];
    const float* bn_gamma     = (const float*)d_in[6];
    const float* bn_beta      = (const float*)d_in[7];
    const float* res_w        = (const float*)d_in[8];
    const float* res_b        = (const float*)d_in[9];
    const float* res_bn_gamma = (const float*)d_in[10];
    const float* res_bn_beta  = (const float*)d_in[11];
    float* out = (float*)d_out;

    cudaFuncSetAttribute(res_gemm_tc, cudaFuncAttributeMaxDynamicSharedMemorySize,
                         RES_SMEM_BYTES);
    cudaFuncSetAttribute(main_gemm_tc, cudaFuncAttributeMaxDynamicSharedMemorySize,
                         MAIN_SMEM_BYTES);

    prep_kernel<<<25, 32>>>(hop, emb, A, b_block);
    cvt_resw_kernel<<<32, 256>>>(res_w);
    gbuild_kernel<<<dim3(33, 8), 256>>>(w_block);
    xprep_kernel<<<dim3(16, 8, 8), 256>>>(x);
    res_gemm_tc<<<dim3(25, 2, 16), 256, RES_SMEM_BYTES>>>(res_b);
    main_gemm_tc<<<dim3(16, 7, 8), 256, MAIN_SMEM_BYTES>>>();
    stats_kernel<<<512, 128>>>(bn_gamma, bn_beta, res_bn_gamma, res_bn_beta);
    final_kernel<<<2048, 256>>>(out);
}

// round 11
// speedup vs baseline: 2.1391x; 1.1005x over previous
#include <cuda_runtime.h>
#include <cuda_fp16.h>
#include <math.h>
#include <stdint.h>

// Problem constants
// N=16, C=128, T=128, V=25, K=3, H=8, OC=256, C/H=16, OC/H=32
// x: (16,128,128,25)  out: (16,256,128,25)

#define TV 3200          // T*V
#define CTV 409600       // C*T*V

// ---- scratch (device globals; allocation-free) ----
__device__ float d_BnA[24 * 625];
__device__ float d_bsum[256];
__device__ __align__(16) __half d_res_preh[16 * 256 * 3200];   // [n][ch][t][w]
__device__ __align__(16) __half d_out_preh[16 * 256 * 3200];   // [n][ch][t][w]
__device__ __align__(16) __half d_G2h[8 * 896 * 400];   // fused weights fp16
__device__ __align__(16) __half d_xrh[16 * 8 * 128 * 400]; // x for main GEMM
__device__ __align__(16) __half d_xth[16 * 3200 * 128];    // x for res GEMM
__device__ __align__(16) __half d_rwh[256 * 128];          // res_w fp16
__device__ float d_ss[1024];
__device__ float d_rpart[800 * 256];             // res-path BN partials
__device__ float d_mpart[8 * 7 * 16 * 128 * 2];  // main-path BN partials

__device__ __forceinline__ void mma_f16(float c[4], const uint32_t a[4],
                                        const uint32_t b[2]) {
    asm volatile(
        "mma.sync.aligned.m16n8k16.row.col.f32.f16.f16.f32 "
        "{%0,%1,%2,%3},{%4,%5,%6,%7},{%8,%9},{%0,%1,%2,%3};"
        : "+f"(c[0]), "+f"(c[1]), "+f"(c[2]), "+f"(c[3])
        : "r"(a[0]), "r"(a[1]), "r"(a[2]), "r"(a[3]), "r"(b[0]), "r"(b[1]));
}
__device__ __forceinline__ uint32_t s2u(const void* p) {
    return (uint32_t)__cvta_generic_to_shared(p);
}
#define LDSM4(r0, r1, r2, r3, addr)                                        \
    asm volatile("ldmatrix.sync.aligned.m8n8.x4.shared.b16 {%0,%1,%2,%3},[%4];" \
                 : "=r"(r0), "=r"(r1), "=r"(r2), "=r"(r3) : "r"(addr))

// ---------------------------------------------------------------------------
// Kernel 1: build BnA and summed bias.
// ---------------------------------------------------------------------------
__global__ void prep_kernel(const int* __restrict__ hop,
                            const float* __restrict__ emb,
                            const float* __restrict__ A,
                            const float* __restrict__ b_block) {
    int g = blockIdx.x;
    int w = threadIdx.x;
    if (g < 24) {
        if (w < 25) {
            const float* eg = emb + g * 12;
            const float* Ag = A + g * 625;
            float sb = 0.f, sa = 0.f;
            for (int v = 0; v < 25; ++v) {
                float bv = eg[hop[v * 25 + w]];
                float av = Ag[v * 25 + w];
                sb += bv * bv;
                sa += av * av;
            }
            float rb = 1.f / (sqrtf(sb) + 1e-4f);
            float ra = 1.f / (sqrtf(sa) + 1e-4f);
            for (int v = 0; v < 25; ++v) {
                float bv = eg[hop[v * 25 + w]];
                float av = Ag[v * 25 + w];
                d_BnA[g * 625 + v * 25 + w] = bv * rb + av * ra;
            }
        }
    } else {
        for (int oc = w; oc < 256; oc += 32)
            d_bsum[oc] = b_block[oc] + b_block[256 + oc] + b_block[512 + oc];
    }
}

// ---------------------------------------------------------------------------
// Kernel 1a: convert res_w -> fp16.
// ---------------------------------------------------------------------------
__global__ __launch_bounds__(256) void cvt_resw_kernel(
    const float* __restrict__ res_w) {
    int idx = (blockIdx.x * 256 + threadIdx.x) * 4;
    float4 v = *(const float4*)(res_w + idx);
    __half2* dst = (__half2*)(d_rwh + idx);
    dst[0] = __floats2half2_rn(v.x, v.y);
    dst[1] = __floats2half2_rn(v.z, v.w);
}

// ---------------------------------------------------------------------------
// Kernel 1b: G2h[h][o*25+w][c*25+v] = sum_k wg*BnA, fp16.
// ---------------------------------------------------------------------------
__global__ __launch_bounds__(256) void gbuild_kernel(
    const float* __restrict__ w_block) {
    int o = blockIdx.x;   // 0..32 (32 = row-pad block)
    int h = blockIdx.y;
    int tid = threadIdx.x;
    if (o == 32) {
        __half* dst = d_G2h + (h * 896 + 800) * 400;
        for (int idx = tid; idx < 96 * 400; idx += 256) dst[idx] = __half(0.f);
        return;
    }
    __shared__ float bna[3 * 625];
    __shared__ float wg3[48];
    for (int idx = tid; idx < 1875; idx += 256) {
        int k = idx / 625;
        bna[idx] = d_BnA[(k * 8 + h) * 625 + (idx - k * 625)];
    }
    if (tid < 48) {
        int k = tid / 16, c = tid & 15;
        wg3[tid] = w_block[(k * 8 + h) * 512 + o * 16 + c];
    }
    __syncthreads();
    __half* dst = d_G2h + (h * 896 + o * 25) * 400;
    for (int idx = tid; idx < 10000; idx += 256) {   // 25 w x 400 cv
        int w = idx / 400, cv = idx - w * 400;
        int c = cv / 25, v = cv - c * 25;
        int vw = v * 25 + w;
        float val = wg3[c] * bna[vw] + wg3[16 + c] * bna[625 + vw] +
                    wg3[32 + c] * bna[1250 + vw];
        dst[w * 400 + cv] = __float2half_rn(val);
    }
}

// ---------------------------------------------------------------------------
// Kernel 1c: unified x prep. Grid (16 n, 8 h, 8 tc).
// ---------------------------------------------------------------------------
__global__ __launch_bounds__(256) void xprep_kernel(const float* __restrict__ x) {
    __shared__ __align__(16) float xs[16 * 404];
    int n = blockIdx.x, h = blockIdx.y, tc = blockIdx.z;
    int tid = threadIdx.x;
    const float* xb = x + n * CTV + h * 16 * TV + tc * 400;

    // Load slab: 16 rows x 400 floats = 1600 float4
#pragma unroll
    for (int it = 0; it < 7; ++it) {
        int idx = tid + it * 256;
        if (idx < 1600) {
            int c = idx / 100, f = idx - c * 100;
            *(float4*)(xs + c * 404 + f * 4) = *(const float4*)(xb + c * TV + f * 4);
        }
    }
    __syncthreads();

    // d_xth[n][tv][h*16+c]: 400 tv x 2 uint4 (8 halves each)
#pragma unroll
    for (int it = 0; it < 4; ++it) {
        int id = tid + it * 256;
        if (id < 800) {
            int tv = id >> 1, q = id & 1;
            __half hbuf[8];
#pragma unroll
            for (int cc = 0; cc < 8; ++cc)
                hbuf[cc] = __float2half_rn(xs[(q * 8 + cc) * 404 + tv]);
            *(uint4*)(d_xth + (n * 3200 + tc * 400 + tv) * 128 + h * 16 + q * 8) =
                *(uint4*)hbuf;
        }
    }
    // d_xrh[n][h][t][c*25+v]: half2 stores (3200 half2 per slab)
    __half2* dstr = (__half2*)(d_xrh + ((n * 8 + h) * 128 + tc * 16) * 400);
#pragma unroll
    for (int it = 0; it < 13; ++it) {
        int idx = tid + it * 256;
        if (idx < 3200) {
            int t = idx / 200;
            int j2 = idx - t * 200;
            int k0 = j2 * 2;
            int c = k0 / 25;
            int v = k0 - c * 25;
            float e0 = xs[c * 404 + t * 25 + v];
            int c1 = (v == 24) ? c + 1 : c;
            int v1 = (v == 24) ? 0 : v + 1;
            float e1 = xs[c1 * 404 + t * 25 + v1];
            dstr[idx] = __floats2half2_rn(e0, e1);
        }
    }
}

// ---------------------------------------------------------------------------
// Kernel 2: res GEMM fp16 m16n8k16 with ldmatrix fragment loads.
// smem rows 136 halves = 272 B (17x16B, conflict-free ldmatrix phases).
// ---------------------------------------------------------------------------
#define RES_SMEM_BYTES (34816 * 2 + 2048)

__global__ __launch_bounds__(256, 2) void res_gemm_tc(
    const float* __restrict__ res_b) {
    extern __shared__ __align__(16) char smem[];
    __half* As = (__half*)smem;                 // [o 128][136]
    __half* Bs = (__half*)(smem + 34816);       // [tv 128][136]
    float* part = (float*)(smem + 69632);

    const int tid = threadIdx.x;
    const int wid = tid >> 5, lane = tid & 31;
    const int gid = lane >> 2, tg = lane & 3;
    const int warp_m = wid >> 1;
    const int warp_n = wid & 1;
    const int tv0 = blockIdx.x * 128;
    const int o0 = blockIdx.y * 128;
    const int n = blockIdx.z;

    {
        const uint4* src = (const uint4*)(d_rwh + o0 * 128);
#pragma unroll
        for (int it = 0; it < 8; ++it) {
            int idx = tid + it * 256;            // 0..2047
            int row = idx >> 4, f = idx & 15;
            *(uint4*)(As + row * 136 + f * 8) = src[row * 16 + f];
        }
    }
    {
        const uint4* src = (const uint4*)(d_xth + (n * 3200 + tv0) * 128);
#pragma unroll
        for (int it = 0; it < 8; ++it) {
            int idx = tid + it * 256;
            int row = idx >> 4, f = idx & 15;
            *(uint4*)(Bs + row * 136 + f * 8) = src[row * 16 + f];
        }
    }
    __syncthreads();

    float c[2][8][4];
#pragma unroll
    for (int mt = 0; mt < 2; ++mt)
#pragma unroll
        for (int nt = 0; nt < 8; ++nt)
#pragma unroll
            for (int q = 0; q < 4; ++q) c[mt][nt][q] = 0.f;

    // ldmatrix lane addresses
    uint32_t aAddr[2], bAddr[4];
    {
        uint32_t As_u = s2u(As), Bs_u = s2u(Bs);
        int r8 = (lane & 7);
#pragma unroll
        for (int mt = 0; mt < 2; ++mt) {
            int row = warp_m * 32 + mt * 16 + r8 + ((lane & 8) ? 8 : 0);
            aAddr[mt] = As_u + row * 272 + ((lane & 16) ? 16 : 0);
        }
#pragma unroll
        for (int p = 0; p < 4; ++p) {
            int row = warp_n * 64 + p * 16 + r8 + ((lane & 16) ? 8 : 0);
            bAddr[p] = Bs_u + row * 272 + ((lane & 8) ? 16 : 0);
        }
    }

#pragma unroll
    for (int step = 0; step < 8; ++step) {
        uint32_t a[2][4], b[8][2];
#pragma unroll
        for (int mt = 0; mt < 2; ++mt)
            LDSM4(a[mt][0], a[mt][1], a[mt][2], a[mt][3], aAddr[mt] + step * 32);
#pragma unroll
        for (int p = 0; p < 4; ++p) {
            uint32_t r0, r1, r2, r3;
            LDSM4(r0, r1, r2, r3, bAddr[p] + step * 32);
            b[2 * p][0] = r0;  b[2 * p][1] = r1;
            b[2 * p + 1][0] = r2;  b[2 * p + 1][1] = r3;
        }
#pragma unroll
        for (int mt = 0; mt < 2; ++mt)
#pragma unroll
            for (int nt = 0; nt < 8; ++nt)
                mma_f16(c[mt][nt], a[mt], b[nt]);
    }

    const int colbase = tv0 + warp_n * 64 + 2 * tg;
#pragma unroll
    for (int mt = 0; mt < 2; ++mt) {
        int row0 = o0 + warp_m * 32 + mt * 16 + gid;
        float bias0 = res_b[row0];
        float bias1 = res_b[row0 + 8];
        float s0 = 0.f, q0 = 0.f, s1 = 0.f, q1 = 0.f;
        __half* dst0 = d_res_preh + (n * 256 + row0) * TV;
        __half* dst1 = dst0 + 8 * TV;
#pragma unroll
        for (int nt = 0; nt < 8; ++nt) {
            float v0 = c[mt][nt][0] + bias0;
            float v1 = c[mt][nt][1] + bias0;
            float v2 = c[mt][nt][2] + bias1;
            float v3 = c[mt][nt][3] + bias1;
            s0 += v0 + v1;  q0 += v0 * v0 + v1 * v1;
            s1 += v2 + v3;  q1 += v2 * v2 + v3 * v3;
            int col = colbase + nt * 8;
            *(__half2*)(dst0 + col) = __floats2half2_rn(v0, v1);
            *(__half2*)(dst1 + col) = __floats2half2_rn(v2, v3);
        }
#pragma unroll
        for (int off = 1; off <= 2; off <<= 1) {
            s0 += __shfl_xor_sync(0xFFFFFFFFu, s0, off);
            q0 += __shfl_xor_sync(0xFFFFFFFFu, q0, off);
            s1 += __shfl_xor_sync(0xFFFFFFFFu, s1, off);
            q1 += __shfl_xor_sync(0xFFFFFFFFu, q1, off);
        }
        if (tg == 0) {
            int r = warp_m * 32 + mt * 16 + gid;
            part[(warp_n * 128 + r) * 2] = s0;
            part[(warp_n * 128 + r) * 2 + 1] = q0;
            part[(warp_n * 128 + r + 8) * 2] = s1;
            part[(warp_n * 128 + r + 8) * 2 + 1] = q1;
        }
    }
    __syncthreads();
    if (tid < 128) {
        float s = part[tid * 2] + part[(128 + tid) * 2];
        float q = part[tid * 2 + 1] + part[(128 + tid) * 2 + 1];
        int blk = (n * 2 + blockIdx.y) * 25 + blockIdx.x;
        d_rpart[blk * 256 + tid * 2] = s;
        d_rpart[blk * 256 + tid * 2 + 1] = q;
    }
}

// ---------------------------------------------------------------------------
// Kernel 3: main fused GEMM fp16 with ldmatrix. smem rows 88 halves = 176 B.
// Output now canonical [n][ch][t][w].
// ---------------------------------------------------------------------------
#define MAIN_SMEM_BYTES (22528 * 2 + 2048)

__global__ __launch_bounds__(256, 2) void main_gemm_tc() {
    extern __shared__ __align__(16) char smem[];
    __half* As = (__half*)smem;                 // [128 rows][88]
    __half* Bs = (__half*)(smem + 22528);       // [128 t][88]
    float* part = (float*)(smem + 45056);

    const int tid = threadIdx.x;
    const int wid = tid >> 5, lane = tid & 31;
    const int gid = lane >> 2, tg = lane & 3;
    const int warp_m = wid >> 1;
    const int warp_n = wid & 1;
    const int n = blockIdx.x;
    const int mb = blockIdx.y;
    const int m0 = mb * 128;
    const int h = blockIdx.z;

    float c[2][8][4];
#pragma unroll
    for (int mt = 0; mt < 2; ++mt)
#pragma unroll
        for (int nt = 0; nt < 8; ++nt)
#pragma unroll
            for (int q = 0; q < 4; ++q) c[mt][nt][q] = 0.f;

    uint32_t aAddr[2], bAddr[4];
    {
        uint32_t As_u = s2u(As), Bs_u = s2u(Bs);
        int r8 = (lane & 7);
#pragma unroll
        for (int mt = 0; mt < 2; ++mt) {
            int row = warp_m * 32 + mt * 16 + r8 + ((lane & 8) ? 8 : 0);
            aAddr[mt] = As_u + row * 176 + ((lane & 16) ? 16 : 0);
        }
#pragma unroll
        for (int p = 0; p < 4; ++p) {
            int row = warp_n * 64 + p * 16 + r8 + ((lane & 16) ? 8 : 0);
            bAddr[p] = Bs_u + row * 176 + ((lane & 8) ? 16 : 0);
        }
    }

    const __half* gbase = d_G2h + (h * 896 + m0) * 400;
    const __half* xbase = d_xrh + (n * 8 + h) * 128 * 400;

    for (int q = 0; q < 5; ++q) {
        const int kc0 = q * 80;                  // halves
        __syncthreads();
#pragma unroll
        for (int it = 0; it < 5; ++it) {
            int idx = tid + it * 256;            // 0..1279
            int row = idx / 10, f = idx - row * 10;
            *(uint4*)(As + row * 88 + f * 8) =
                *(const uint4*)(gbase + row * 400 + kc0 + f * 8);
        }
#pragma unroll
        for (int it = 0; it < 5; ++it) {
            int idx = tid + it * 256;
            int row = idx / 10, f = idx - row * 10;
            *(uint4*)(Bs + row * 88 + f * 8) =
                *(const uint4*)(xbase + row * 400 + kc0 + f * 8);
        }
        __syncthreads();

#pragma unroll
        for (int step = 0; step < 5; ++step) {
            uint32_t a[2][4], b[8][2];
#pragma unroll
            for (int mt = 0; mt < 2; ++mt)
                LDSM4(a[mt][0], a[mt][1], a[mt][2], a[mt][3], aAddr[mt] + step * 32);
#pragma unroll
            for (int p = 0; p < 4; ++p) {
                uint32_t r0, r1, r2, r3;
                LDSM4(r0, r1, r2, r3, bAddr[p] + step * 32);
                b[2 * p][0] = r0;  b[2 * p][1] = r1;
                b[2 * p + 1][0] = r2;  b[2 * p + 1][1] = r3;
            }
#pragma unroll
            for (int mt = 0; mt < 2; ++mt)
#pragma unroll
                for (int nt = 0; nt < 8; ++nt)
                    mma_f16(c[mt][nt], a[mt], b[nt]);
        }
    }

    // Epilogue: bias, canonical-layout fp16 stores, BN partials.
    __half* obase = d_out_preh + (n * 256 + h * 32) * TV;
#pragma unroll
    for (int mt = 0; mt < 2; ++mt) {
        int r0 = m0 + warp_m * 32 + mt * 16 + gid;
        int r1 = r0 + 8;
        int o0 = r0 / 25, o1 = r1 / 25;
        int w0 = r0 - o0 * 25, w1 = r1 - o1 * 25;
        float bias0 = (r0 < 800) ? d_bsum[h * 32 + o0] : 0.f;
        float bias1 = (r1 < 800) ? d_bsum[h * 32 + o1] : 0.f;
        float s0 = 0.f, q0 = 0.f, s1 = 0.f, q1 = 0.f;
        int colbase = warp_n * 64 + 2 * tg;
#pragma unroll
        for (int nt = 0; nt < 8; ++nt) {
            float v0 = c[mt][nt][0] + bias0;
            float v1 = c[mt][nt][1] + bias0;
            float v2 = c[mt][nt][2] + bias1;
            float v3 = c[mt][nt][3] + bias1;
            s0 += v0 + v1;  q0 += v0 * v0 + v1 * v1;
            s1 += v2 + v3;  q1 += v2 * v2 + v3 * v3;
            int col = colbase + nt * 8;         // t index
            if (r0 < 800) {
                __half* d0 = obase + o0 * TV + col * 25 + w0;
                d0[0] = __float2half_rn(v0);
                d0[25] = __float2half_rn(v1);
            }
            if (r1 < 800) {
                __half* d1 = obase + o1 * TV + col * 25 + w1;
                d1[0] = __float2half_rn(v2);
                d1[25] = __float2half_rn(v3);
            }
        }
#pragma unroll
        for (int off = 1; off <= 2; off <<= 1) {
            s0 += __shfl_xor_sync(0xFFFFFFFFu, s0, off);
            q0 += __shfl_xor_sync(0xFFFFFFFFu, q0, off);
            s1 += __shfl_xor_sync(0xFFFFFFFFu, s1, off);
            q1 += __shfl_xor_sync(0xFFFFFFFFu, q1, off);
        }
        if (tg == 0) {
            int r = warp_m * 32 + mt * 16 + gid;
            part[(warp_n * 128 + r) * 2] = s0;
            part[(warp_n * 128 + r) * 2 + 1] = q0;
            part[(warp_n * 128 + r + 8) * 2] = s1;
            part[(warp_n * 128 + r + 8) * 2 + 1] = q1;
        }
    }
    __syncthreads();
    if (tid < 128) {
        float s = part[tid * 2] + part[(128 + tid) * 2];
        float q = part[tid * 2 + 1] + part[(128 + tid) * 2 + 1];
        int blk = (h * 7 + mb) * 16 + n;
        d_mpart[(blk * 128 + tid) * 2] = s;
        d_mpart[(blk * 128 + tid) * 2 + 1] = q;
    }
}

// ---------------------------------------------------------------------------
// Kernel 4: merged BN stats (both paths). Grid 512: which = blk>>8.
// ---------------------------------------------------------------------------
__global__ __launch_bounds__(128) void stats_kernel(
    const float* __restrict__ bn_gamma, const float* __restrict__ bn_beta,
    const float* __restrict__ res_bn_gamma, const float* __restrict__ res_bn_beta) {
    __shared__ float ssum[128];
    __shared__ float ssq[128];
    int which = blockIdx.x >> 8;
    int ch = blockIdx.x & 255;
    int tid = threadIdx.x;

    float s = 0.f, q = 0.f;
    if (which == 0) {
        int h = ch >> 5, o = ch & 31;
        for (int e = tid; e < 400; e += 128) {
            int w = e >> 4, nn = e & 15;
            int grow = o * 25 + w;
            int mb = grow >> 7, lr = grow & 127;
            int blk = (h * 7 + mb) * 16 + nn;
            s += d_mpart[(blk * 128 + lr) * 2];
            q += d_mpart[(blk * 128 + lr) * 2 + 1];
        }
    } else {
        int ob = ch >> 7, row = ch & 127;
        for (int e = tid; e < 400; e += 128) {
            int nn = e / 25, tvb = e - nn * 25;
            int blk = (nn * 2 + ob) * 25 + tvb;
            s += d_rpart[blk * 256 + row * 2];
            q += d_rpart[blk * 256 + row * 2 + 1];
        }
    }
    ssum[tid] = s;
    ssq[tid] = q;
    __syncthreads();
    for (int st = 64; st > 0; st >>= 1) {
        if (tid < st) {
            ssum[tid] += ssum[tid + st];
            ssq[tid] += ssq[tid + st];
        }
        __syncthreads();
    }
    if (tid == 0) {
        const float inv = 1.f / 51200.f;
        float mean = ssum[0] * inv;
        float var = ssq[0] * inv - mean * mean;
        float g = which ? res_bn_gamma[ch] : bn_gamma[ch];
        float b = which ? res_bn_beta[ch] : bn_beta[ch];
        float sc = g * rsqrtf(var + 1e-5f);
        d_ss[which * 512 + ch] = sc;
        d_ss[which * 512 + 256 + ch] = b - mean * sc;
    }
}

// ---------------------------------------------------------------------------
// Kernel 5: out = relu(BN(out_preh) + BN(res_preh)). Block per (n,ch);
// both inputs canonical [n][ch][t][w] -> pure streaming.
// ---------------------------------------------------------------------------
__global__ __launch_bounds__(256) void final_kernel(float* __restrict__ out) {
    int b = blockIdx.x;                 // n*256 + ch
    int ch = b & 255;
    int tid = threadIdx.x;
    const uint2* po = (const uint2*)(d_out_preh + b * TV);
    const uint2* pr = (const uint2*)(d_res_preh + b * TV);
    float4* dst = (float4*)(out + b * TV);
    float so = d_ss[ch], ho = d_ss[256 + ch];
    float sr = d_ss[512 + ch], hr = d_ss[768 + ch];
#pragma unroll
    for (int it = 0; it < 4; ++it) {
        int idx = tid + it * 256;       // < 800 uint2 (4 halves each)
        if (idx < 800) {
            uint2 ov = po[idx];
            uint2 rv = pr[idx];
            float2 o0 = __half22float2(*(__half2*)&ov.x);
            float2 o1 = __half22float2(*(__half2*)&ov.y);
            float2 r0 = __half22float2(*(__half2*)&rv.x);
            float2 r1 = __half22float2(*(__half2*)&rv.y);
            float4 r;
            r.x = fmaxf(fmaf(o0.x, so, ho) + fmaf(r0.x, sr, hr), 0.f);
            r.y = fmaxf(fmaf(o0.y, so, ho) + fmaf(r0.y, sr, hr), 0.f);
            r.z = fmaxf(fmaf(o1.x, so, ho) + fmaf(r1.x, sr, hr), 0.f);
            r.w = fmaxf(fmaf(o1.y, so, ho) + fmaf(r1.y, sr, hr), 0.f);
            dst[idx] = r;
        }
    }
}

// ---------------------------------------------------------------------------
extern "C" void kernel_launch(void* const* d_in, const int* in_sizes, int n_in,
                              void* d_out, int out_size) {
    const float* x            = (const float*)d_in[0];
    const int*   hop          = (const int*)d_in[1];
    const float* emb          = (const float*)d_in[2];
    const float* A            = (const float*)d_in[3];
    const float* w_block      = (const float*)d_in[4];
    const float* b_block      = (const float*)d_in[5];
    const float* bn_gamma     = (const float*)d_in[6];
    const float* bn_beta      = (const float*)d_in[7];
    const float* res_w        = (const float*)d_in[8];
    const float* res_b        = (const float*)d_in[9];
    const float* res_bn_gamma = (const float*)d_in[10];
    const float* res_bn_beta  = (const float*)d_in[11];
    float* out = (float*)d_out;

    cudaFuncSetAttribute(res_gemm_tc, cudaFuncAttributeMaxDynamicSharedMemorySize,
                         RES_SMEM_BYTES);
    cudaFuncSetAttribute(main_gemm_tc, cudaFuncAttributeMaxDynamicSharedMemorySize,
                         MAIN_SMEM_BYTES);

    prep_kernel<<<25, 32>>>(hop, emb, A, b_block);
    cvt_resw_kernel<<<32, 256>>>(res_w);
    gbuild_kernel<<<dim3(33, 8), 256>>>(w_block);
    xprep_kernel<<<dim3(16, 8, 8), 256>>>(x);
    res_gemm_tc<<<dim3(25, 2, 16), 256, RES_SMEM_BYTES>>>(res_b);
    main_gemm_tc<<<dim3(16, 7, 8), 256, MAIN_SMEM_BYTES>>>();
    stats_kernel<<<512, 128>>>(bn_gamma, bn_beta, res_bn_gamma, res_bn_beta);
    final_kernel<<<4096, 256>>>(out);
}

// round 12
// speedup vs baseline: 2.2066x; 1.0316x over previous
#include <cuda_runtime.h>
#include <cuda_fp16.h>
#include <math.h>
#include <stdint.h>

// Problem constants
// N=16, C=128, T=128, V=25, K=3, H=8, OC=256, C/H=16, OC/H=32
// x: (16,128,128,25)  out: (16,256,128,25)

#define TV 3200          // T*V
#define CTV 409600       // C*T*V

// ---- scratch (device globals; allocation-free) ----
__device__ float d_BnA[24 * 625];
__device__ float d_bsum[256];
__device__ __align__(16) __half d_res_preh[16 * 256 * 3200];   // [n][ch][t][w]
__device__ __align__(16) __half d_out_preh[16 * 256 * 3200];   // [n][ch][t][w]
__device__ __align__(16) __half d_G2h[8 * 896 * 400];   // fused weights fp16
__device__ __align__(16) __half d_xrh[16 * 8 * 128 * 400]; // x for main GEMM
__device__ __align__(16) __half d_xth[16 * 3200 * 128];    // x for res GEMM
__device__ __align__(16) __half d_rwh[256 * 128];          // res_w fp16
__device__ float d_ss[1024];
__device__ float d_rpart[800 * 256];             // res-path BN partials
__device__ float d_mpart[8 * 7 * 16 * 128 * 2];  // main-path BN partials

__device__ __forceinline__ void mma_f16(float c[4], const uint32_t a[4],
                                        const uint32_t b[2]) {
    asm volatile(
        "mma.sync.aligned.m16n8k16.row.col.f32.f16.f16.f32 "
        "{%0,%1,%2,%3},{%4,%5,%6,%7},{%8,%9},{%0,%1,%2,%3};"
        : "+f"(c[0]), "+f"(c[1]), "+f"(c[2]), "+f"(c[3])
        : "r"(a[0]), "r"(a[1]), "r"(a[2]), "r"(a[3]), "r"(b[0]), "r"(b[1]));
}
__device__ __forceinline__ uint32_t s2u(const void* p) {
    return (uint32_t)__cvta_generic_to_shared(p);
}
#define LDSM4(r0, r1, r2, r3, addr)                                        \
    asm volatile("ldmatrix.sync.aligned.m8n8.x4.shared.b16 {%0,%1,%2,%3},[%4];" \
                 : "=r"(r0), "=r"(r1), "=r"(r2), "=r"(r3) : "r"(addr))
__device__ __forceinline__ void cp16(uint32_t dst, const void* src) {
    asm volatile("cp.async.cg.shared.global [%0], [%1], 16;"
                 :: "r"(dst), "l"(src));
}
#define CP_COMMIT() asm volatile("cp.async.commit_group;" ::: "memory")
#define CP_WAIT(n)  asm volatile("cp.async.wait_group %0;" :: "n"(n) : "memory")

// ---------------------------------------------------------------------------
// Kernel 1: build BnA and summed bias.
// ---------------------------------------------------------------------------
__global__ void prep_kernel(const int* __restrict__ hop,
                            const float* __restrict__ emb,
                            const float* __restrict__ A,
                            const float* __restrict__ b_block) {
    int g = blockIdx.x;
    int w = threadIdx.x;
    if (g < 24) {
        if (w < 25) {
            const float* eg = emb + g * 12;
            const float* Ag = A + g * 625;
            float sb = 0.f, sa = 0.f;
            for (int v = 0; v < 25; ++v) {
                float bv = eg[hop[v * 25 + w]];
                float av = Ag[v * 25 + w];
                sb += bv * bv;
                sa += av * av;
            }
            float rb = 1.f / (sqrtf(sb) + 1e-4f);
            float ra = 1.f / (sqrtf(sa) + 1e-4f);
            for (int v = 0; v < 25; ++v) {
                float bv = eg[hop[v * 25 + w]];
                float av = Ag[v * 25 + w];
                d_BnA[g * 625 + v * 25 + w] = bv * rb + av * ra;
            }
        }
    } else {
        for (int oc = w; oc < 256; oc += 32)
            d_bsum[oc] = b_block[oc] + b_block[256 + oc] + b_block[512 + oc];
    }
}

// ---------------------------------------------------------------------------
// Kernel 1a: convert res_w -> fp16.
// ---------------------------------------------------------------------------
__global__ __launch_bounds__(256) void cvt_resw_kernel(
    const float* __restrict__ res_w) {
    int idx = (blockIdx.x * 256 + threadIdx.x) * 4;
    float4 v = *(const float4*)(res_w + idx);
    __half2* dst = (__half2*)(d_rwh + idx);
    dst[0] = __floats2half2_rn(v.x, v.y);
    dst[1] = __floats2half2_rn(v.z, v.w);
}

// ---------------------------------------------------------------------------
// Kernel 1b: G2h[h][o*25+w][c*25+v] = sum_k wg*BnA, fp16.
// ---------------------------------------------------------------------------
__global__ __launch_bounds__(256) void gbuild_kernel(
    const float* __restrict__ w_block) {
    int o = blockIdx.x;   // 0..32 (32 = row-pad block)
    int h = blockIdx.y;
    int tid = threadIdx.x;
    if (o == 32) {
        __half* dst = d_G2h + (h * 896 + 800) * 400;
        for (int idx = tid; idx < 96 * 400; idx += 256) dst[idx] = __half(0.f);
        return;
    }
    __shared__ float bna[3 * 625];
    __shared__ float wg3[48];
    for (int idx = tid; idx < 1875; idx += 256) {
        int k = idx / 625;
        bna[idx] = d_BnA[(k * 8 + h) * 625 + (idx - k * 625)];
    }
    if (tid < 48) {
        int k = tid / 16, c = tid & 15;
        wg3[tid] = w_block[(k * 8 + h) * 512 + o * 16 + c];
    }
    __syncthreads();
    __half* dst = d_G2h + (h * 896 + o * 25) * 400;
    for (int idx = tid; idx < 10000; idx += 256) {   // 25 w x 400 cv
        int w = idx / 400, cv = idx - w * 400;
        int c = cv / 25, v = cv - c * 25;
        int vw = v * 25 + w;
        float val = wg3[c] * bna[vw] + wg3[16 + c] * bna[625 + vw] +
                    wg3[32 + c] * bna[1250 + vw];
        dst[w * 400 + cv] = __float2half_rn(val);
    }
}

// ---------------------------------------------------------------------------
// Kernel 1c: unified x prep. Grid (16 n, 8 h, 8 tc).
// xth via float2 column reads; xrh via per-thread fixed (c,v) march over t.
// ---------------------------------------------------------------------------
__global__ __launch_bounds__(256) void xprep_kernel(const float* __restrict__ x) {
    __shared__ __align__(16) float xs[16 * 404];
    int n = blockIdx.x, h = blockIdx.y, tc = blockIdx.z;
    int tid = threadIdx.x;
    const float* xb = x + n * CTV + h * 16 * TV + tc * 400;

    // Load slab: 16 rows x 400 floats = 1600 float4
#pragma unroll
    for (int it = 0; it < 7; ++it) {
        int idx = tid + it * 256;
        if (idx < 1600) {
            int c = idx / 100, f = idx - c * 100;
            *(float4*)(xs + c * 404 + f * 4) = *(const float4*)(xb + c * TV + f * 4);
        }
    }
    __syncthreads();

    // d_xth[n][tv][h*16+c]: 400 items = (200 tv-pairs) x (2 q-halves)
#pragma unroll
    for (int it = 0; it < 2; ++it) {
        int id = tid + it * 256;
        if (id < 400) {
            int tvp = id >> 1, q = id & 1;
            __half hA[8], hB[8];
#pragma unroll
            for (int cc = 0; cc < 8; ++cc) {
                float2 v = *(const float2*)&xs[(q * 8 + cc) * 404 + tvp * 2];
                hA[cc] = __float2half_rn(v.x);
                hB[cc] = __float2half_rn(v.y);
            }
            __half* base = d_xth + (n * 3200 + tc * 400 + tvp * 2) * 128 + h * 16 + q * 8;
            *(uint4*)base = *(uint4*)hA;
            *(uint4*)(base + 128) = *(uint4*)hB;
        }
    }
    // d_xrh[n][h][t][c*25+v]: thread owns one half2 column, marches t.
    if (tid < 200) {
        int k0 = tid * 2;
        int c0 = k0 / 25, v0 = k0 - c0 * 25;
        int c1 = (v0 == 24) ? c0 + 1 : c0;
        int v1 = (v0 == 24) ? 0 : v0 + 1;
        const float* p0 = &xs[c0 * 404 + v0];
        const float* p1 = &xs[c1 * 404 + v1];
        __half2* dstr = (__half2*)(d_xrh + ((n * 8 + h) * 128 + tc * 16) * 400);
#pragma unroll
        for (int t = 0; t < 16; ++t)
            dstr[t * 200 + tid] = __floats2half2_rn(p0[t * 25], p1[t * 25]);
    }
}

// ---------------------------------------------------------------------------
// Kernel 2: res GEMM fp16 m16n8k16, ldmatrix + cp.async staging.
// ---------------------------------------------------------------------------
#define RES_SMEM_BYTES (34816 * 2 + 2048)

__global__ __launch_bounds__(256, 2) void res_gemm_tc(
    const float* __restrict__ res_b) {
    extern __shared__ __align__(16) char smem[];
    __half* As = (__half*)smem;                 // [o 128][136]
    __half* Bs = (__half*)(smem + 34816);       // [tv 128][136]
    float* part = (float*)(smem + 69632);

    const int tid = threadIdx.x;
    const int wid = tid >> 5, lane = tid & 31;
    const int gid = lane >> 2, tg = lane & 3;
    const int warp_m = wid >> 1;
    const int warp_n = wid & 1;
    const int tv0 = blockIdx.x * 128;
    const int o0 = blockIdx.y * 128;
    const int n = blockIdx.z;

    {
        uint32_t As_u = s2u(As), Bs_u = s2u(Bs);
        const uint4* srcA = (const uint4*)(d_rwh + o0 * 128);
        const uint4* srcB = (const uint4*)(d_xth + (n * 3200 + tv0) * 128);
#pragma unroll
        for (int it = 0; it < 8; ++it) {
            int idx = tid + it * 256;            // 0..2047
            int row = idx >> 4, f = idx & 15;
            cp16(As_u + row * 272 + f * 16, srcA + row * 16 + f);
            cp16(Bs_u + row * 272 + f * 16, srcB + row * 16 + f);
        }
        CP_COMMIT();
        CP_WAIT(0);
    }
    __syncthreads();

    float c[2][8][4];
#pragma unroll
    for (int mt = 0; mt < 2; ++mt)
#pragma unroll
        for (int nt = 0; nt < 8; ++nt)
#pragma unroll
            for (int q = 0; q < 4; ++q) c[mt][nt][q] = 0.f;

    // ldmatrix lane addresses
    uint32_t aAddr[2], bAddr[4];
    {
        uint32_t As_u = s2u(As), Bs_u = s2u(Bs);
        int r8 = (lane & 7);
#pragma unroll
        for (int mt = 0; mt < 2; ++mt) {
            int row = warp_m * 32 + mt * 16 + r8 + ((lane & 8) ? 8 : 0);
            aAddr[mt] = As_u + row * 272 + ((lane & 16) ? 16 : 0);
        }
#pragma unroll
        for (int p = 0; p < 4; ++p) {
            int row = warp_n * 64 + p * 16 + r8 + ((lane & 16) ? 8 : 0);
            bAddr[p] = Bs_u + row * 272 + ((lane & 8) ? 16 : 0);
        }
    }

#pragma unroll
    for (int step = 0; step < 8; ++step) {
        uint32_t a[2][4], b[8][2];
#pragma unroll
        for (int mt = 0; mt < 2; ++mt)
            LDSM4(a[mt][0], a[mt][1], a[mt][2], a[mt][3], aAddr[mt] + step * 32);
#pragma unroll
        for (int p = 0; p < 4; ++p) {
            uint32_t r0, r1, r2, r3;
            LDSM4(r0, r1, r2, r3, bAddr[p] + step * 32);
            b[2 * p][0] = r0;  b[2 * p][1] = r1;
            b[2 * p + 1][0] = r2;  b[2 * p + 1][1] = r3;
        }
#pragma unroll
        for (int mt = 0; mt < 2; ++mt)
#pragma unroll
            for (int nt = 0; nt < 8; ++nt)
                mma_f16(c[mt][nt], a[mt], b[nt]);
    }

    const int colbase = tv0 + warp_n * 64 + 2 * tg;
#pragma unroll
    for (int mt = 0; mt < 2; ++mt) {
        int row0 = o0 + warp_m * 32 + mt * 16 + gid;
        float bias0 = res_b[row0];
        float bias1 = res_b[row0 + 8];
        float s0 = 0.f, q0 = 0.f, s1 = 0.f, q1 = 0.f;
        __half* dst0 = d_res_preh + (n * 256 + row0) * TV;
        __half* dst1 = dst0 + 8 * TV;
#pragma unroll
        for (int nt = 0; nt < 8; ++nt) {
            float v0 = c[mt][nt][0] + bias0;
            float v1 = c[mt][nt][1] + bias0;
            float v2 = c[mt][nt][2] + bias1;
            float v3 = c[mt][nt][3] + bias1;
            s0 += v0 + v1;  q0 += v0 * v0 + v1 * v1;
            s1 += v2 + v3;  q1 += v2 * v2 + v3 * v3;
            int col = colbase + nt * 8;
            *(__half2*)(dst0 + col) = __floats2half2_rn(v0, v1);
            *(__half2*)(dst1 + col) = __floats2half2_rn(v2, v3);
        }
#pragma unroll
        for (int off = 1; off <= 2; off <<= 1) {
            s0 += __shfl_xor_sync(0xFFFFFFFFu, s0, off);
            q0 += __shfl_xor_sync(0xFFFFFFFFu, q0, off);
            s1 += __shfl_xor_sync(0xFFFFFFFFu, s1, off);
            q1 += __shfl_xor_sync(0xFFFFFFFFu, q1, off);
        }
        if (tg == 0) {
            int r = warp_m * 32 + mt * 16 + gid;
            part[(warp_n * 128 + r) * 2] = s0;
            part[(warp_n * 128 + r) * 2 + 1] = q0;
            part[(warp_n * 128 + r + 8) * 2] = s1;
            part[(warp_n * 128 + r + 8) * 2 + 1] = q1;
        }
    }
    __syncthreads();
    if (tid < 128) {
        float s = part[tid * 2] + part[(128 + tid) * 2];
        float q = part[tid * 2 + 1] + part[(128 + tid) * 2 + 1];
        int blk = (n * 2 + blockIdx.y) * 25 + blockIdx.x;
        d_rpart[blk * 256 + tid * 2] = s;
        d_rpart[blk * 256 + tid * 2 + 1] = q;
    }
}

// ---------------------------------------------------------------------------
// Kernel 3: main fused GEMM fp16, ldmatrix + double-buffered cp.async pipeline.
// Buffers: A0@0, B0@22528, A1@45056, B1@67584, part@90112. 92160 B total.
// ---------------------------------------------------------------------------
#define MAIN_SMEM_BYTES (90112 + 2048)
#define BUFSZ 45056

__global__ __launch_bounds__(256, 2) void main_gemm_tc() {
    extern __shared__ __align__(16) char smem[];
    float* part = (float*)(smem + 90112);

    const int tid = threadIdx.x;
    const int wid = tid >> 5, lane = tid & 31;
    const int gid = lane >> 2, tg = lane & 3;
    const int warp_m = wid >> 1;
    const int warp_n = wid & 1;
    const int n = blockIdx.x;
    const int mb = blockIdx.y;
    const int m0 = mb * 128;
    const int h = blockIdx.z;

    float c[2][8][4];
#pragma unroll
    for (int mt = 0; mt < 2; ++mt)
#pragma unroll
        for (int nt = 0; nt < 8; ++nt)
#pragma unroll
            for (int q = 0; q < 4; ++q) c[mt][nt][q] = 0.f;

    const uint32_t smem_u = s2u(smem);
    const __half* gbase = d_G2h + (h * 896 + m0) * 400;
    const __half* xbase = d_xrh + (n * 8 + h) * 128 * 400;

    // ldmatrix lane addresses (buffer 0 base; add buf*BUFSZ)
    uint32_t aAddr[2], bAddr[4];
    {
        int r8 = (lane & 7);
#pragma unroll
        for (int mt = 0; mt < 2; ++mt) {
            int row = warp_m * 32 + mt * 16 + r8 + ((lane & 8) ? 8 : 0);
            aAddr[mt] = smem_u + row * 176 + ((lane & 16) ? 16 : 0);
        }
#pragma unroll
        for (int p = 0; p < 4; ++p) {
            int row = warp_n * 64 + p * 16 + r8 + ((lane & 16) ? 8 : 0);
            bAddr[p] = smem_u + 22528 + row * 176 + ((lane & 8) ? 16 : 0);
        }
    }

    // staging indices (constant per thread)
    const int srow = tid / 10 * 0;  // placeholder to keep regs low (unused)
    (void)srow;

    // issue chunk 0 into buffer 0
    {
#pragma unroll
        for (int it = 0; it < 5; ++it) {
            int idx = tid + it * 256;
            int row = idx / 10, f = idx - row * 10;
            cp16(smem_u + row * 176 + f * 16, gbase + row * 400 + f * 8);
            cp16(smem_u + 22528 + row * 176 + f * 16, xbase + row * 400 + f * 8);
        }
        CP_COMMIT();
    }

    for (int q = 0; q < 5; ++q) {
        const int buf = q & 1;
        // issue next chunk into other buffer (it was last read in iter q-1,
        // protected by trailing __syncthreads of iter q-1)
        if (q + 1 < 5) {
            const int nb = (q + 1) & 1;
            const int kc = (q + 1) * 80;
#pragma unroll
            for (int it = 0; it < 5; ++it) {
                int idx = tid + it * 256;
                int row = idx / 10, f = idx - row * 10;
                cp16(smem_u + nb * BUFSZ + row * 176 + f * 16,
                     gbase + row * 400 + kc + f * 8);
                cp16(smem_u + nb * BUFSZ + 22528 + row * 176 + f * 16,
                     xbase + row * 400 + kc + f * 8);
            }
            CP_COMMIT();
            CP_WAIT(1);          // chunk q complete; q+1 may be in flight
        } else {
            CP_WAIT(0);
        }
        __syncthreads();

        const uint32_t boff = buf * BUFSZ;
#pragma unroll
        for (int step = 0; step < 5; ++step) {
            uint32_t a[2][4], b[8][2];
#pragma unroll
            for (int mt = 0; mt < 2; ++mt)
                LDSM4(a[mt][0], a[mt][1], a[mt][2], a[mt][3],
                      aAddr[mt] + boff + step * 32);
#pragma unroll
            for (int p = 0; p < 4; ++p) {
                uint32_t r0, r1, r2, r3;
                LDSM4(r0, r1, r2, r3, bAddr[p] + boff + step * 32);
                b[2 * p][0] = r0;  b[2 * p][1] = r1;
                b[2 * p + 1][0] = r2;  b[2 * p + 1][1] = r3;
            }
#pragma unroll
            for (int mt = 0; mt < 2; ++mt)
#pragma unroll
                for (int nt = 0; nt < 8; ++nt)
                    mma_f16(c[mt][nt], a[mt], b[nt]);
        }
        __syncthreads();
    }

    // Epilogue: bias, canonical-layout fp16 stores, BN partials.
    __half* obase = d_out_preh + (n * 256 + h * 32) * TV;
#pragma unroll
    for (int mt = 0; mt < 2; ++mt) {
        int r0 = m0 + warp_m * 32 + mt * 16 + gid;
        int r1 = r0 + 8;
        int o0 = r0 / 25, o1 = r1 / 25;
        int w0 = r0 - o0 * 25, w1 = r1 - o1 * 25;
        float bias0 = (r0 < 800) ? d_bsum[h * 32 + o0] : 0.f;
        float bias1 = (r1 < 800) ? d_bsum[h * 32 + o1] : 0.f;
        float s0 = 0.f, q0 = 0.f, s1 = 0.f, q1 = 0.f;
        int colbase = warp_n * 64 + 2 * tg;
#pragma unroll
        for (int nt = 0; nt < 8; ++nt) {
            float v0 = c[mt][nt][0] + bias0;
            float v1 = c[mt][nt][1] + bias0;
            float v2 = c[mt][nt][2] + bias1;
            float v3 = c[mt][nt][3] + bias1;
            s0 += v0 + v1;  q0 += v0 * v0 + v1 * v1;
            s1 += v2 + v3;  q1 += v2 * v2 + v3 * v3;
            int col = colbase + nt * 8;         // t index
            if (r0 < 800) {
                __half* d0 = obase + o0 * TV + col * 25 + w0;
                d0[0] = __float2half_rn(v0);
                d0[25] = __float2half_rn(v1);
            }
            if (r1 < 800) {
                __half* d1 = obase + o1 * TV + col * 25 + w1;
                d1[0] = __float2half_rn(v2);
                d1[25] = __float2half_rn(v3);
            }
        }
#pragma unroll
        for (int off = 1; off <= 2; off <<= 1) {
            s0 += __shfl_xor_sync(0xFFFFFFFFu, s0, off);
            q0 += __shfl_xor_sync(0xFFFFFFFFu, q0, off);
            s1 += __shfl_xor_sync(0xFFFFFFFFu, s1, off);
            q1 += __shfl_xor_sync(0xFFFFFFFFu, q1, off);
        }
        if (tg == 0) {
            int r = warp_m * 32 + mt * 16 + gid;
            part[(warp_n * 128 + r) * 2] = s0;
            part[(warp_n * 128 + r) * 2 + 1] = q0;
            part[(warp_n * 128 + r + 8) * 2] = s1;
            part[(warp_n * 128 + r + 8) * 2 + 1] = q1;
        }
    }
    __syncthreads();
    if (tid < 128) {
        float s = part[tid * 2] + part[(128 + tid) * 2];
        float q = part[tid * 2 + 1] + part[(128 + tid) * 2 + 1];
        int blk = (h * 7 + mb) * 16 + n;
        d_mpart[(blk * 128 + tid) * 2] = s;
        d_mpart[(blk * 128 + tid) * 2 + 1] = q;
    }
}

// ---------------------------------------------------------------------------
// Kernel 4: merged BN stats (both paths). Grid 512: which = blk>>8.
// ---------------------------------------------------------------------------
__global__ __launch_bounds__(128) void stats_kernel(
    const float* __restrict__ bn_gamma, const float* __restrict__ bn_beta,
    const float* __restrict__ res_bn_gamma, const float* __restrict__ res_bn_beta) {
    __shared__ float ssum[128];
    __shared__ float ssq[128];
    int which = blockIdx.x >> 8;
    int ch = blockIdx.x & 255;
    int tid = threadIdx.x;

    float s = 0.f, q = 0.f;
    if (which == 0) {
        int h = ch >> 5, o = ch & 31;
        for (int e = tid; e < 400; e += 128) {
            int w = e >> 4, nn = e & 15;
            int grow = o * 25 + w;
            int mb = grow >> 7, lr = grow & 127;
            int blk = (h * 7 + mb) * 16 + nn;
            s += d_mpart[(blk * 128 + lr) * 2];
            q += d_mpart[(blk * 128 + lr) * 2 + 1];
        }
    } else {
        int ob = ch >> 7, row = ch & 127;
        for (int e = tid; e < 400; e += 128) {
            int nn = e / 25, tvb = e - nn * 25;
            int blk = (nn * 2 + ob) * 25 + tvb;
            s += d_rpart[blk * 256 + row * 2];
            q += d_rpart[blk * 256 + row * 2 + 1];
        }
    }
    ssum[tid] = s;
    ssq[tid] = q;
    __syncthreads();
    for (int st = 64; st > 0; st >>= 1) {
        if (tid < st) {
            ssum[tid] += ssum[tid + st];
            ssq[tid] += ssq[tid + st];
        }
        __syncthreads();
    }
    if (tid == 0) {
        const float inv = 1.f / 51200.f;
        float mean = ssum[0] * inv;
        float var = ssq[0] * inv - mean * mean;
        float g = which ? res_bn_gamma[ch] : bn_gamma[ch];
        float b = which ? res_bn_beta[ch] : bn_beta[ch];
        float sc = g * rsqrtf(var + 1e-5f);
        d_ss[which * 512 + ch] = sc;
        d_ss[which * 512 + 256 + ch] = b - mean * sc;
    }
}

// ---------------------------------------------------------------------------
// Kernel 5: out = relu(BN(out_preh) + BN(res_preh)). Block per (n,ch).
// ---------------------------------------------------------------------------
__global__ __launch_bounds__(256) void final_kernel(float* __restrict__ out) {
    int b = blockIdx.x;                 // n*256 + ch
    int ch = b & 255;
    int tid = threadIdx.x;
    const uint2* po = (const uint2*)(d_out_preh + b * TV);
    const uint2* pr = (const uint2*)(d_res_preh + b * TV);
    float4* dst = (float4*)(out + b * TV);
    float so = d_ss[ch], ho = d_ss[256 + ch];
    float sr = d_ss[512 + ch], hr = d_ss[768 + ch];
#pragma unroll
    for (int it = 0; it < 4; ++it) {
        int idx = tid + it * 256;       // < 800 uint2 (4 halves each)
        if (idx < 800) {
            uint2 ov = po[idx];
            uint2 rv = pr[idx];
            float2 o0 = __half22float2(*(__half2*)&ov.x);
            float2 o1 = __half22float2(*(__half2*)&ov.y);
            float2 r0 = __half22float2(*(__half2*)&rv.x);
            float2 r1 = __half22float2(*(__half2*)&rv.y);
            float4 r;
            r.x = fmaxf(fmaf(o0.x, so, ho) + fmaf(r0.x, sr, hr), 0.f);
            r.y = fmaxf(fmaf(o0.y, so, ho) + fmaf(r0.y, sr, hr), 0.f);
            r.z = fmaxf(fmaf(o1.x, so, ho) + fmaf(r1.x, sr, hr), 0.f);
            r.w = fmaxf(fmaf(o1.y, so, ho) + fmaf(r1.y, sr, hr), 0.f);
            dst[idx] = r;
        }
    }
}

// ---------------------------------------------------------------------------
extern "C" void kernel_launch(void* const* d_in, const int* in_sizes, int n_in,
                              void* d_out, int out_size) {
    const float* x            = (const float*)d_in[0];
    const int*   hop          = (const int*)d_in[1];
    const float* emb          = (const float*)d_in[2];
    const float* A            = (const float*)d_in[3];
    const float* w_block      = (const float*)d_in[4];
    const float* b_block      = (const float*)d_in[5];
    const float* bn_gamma     = (const float*)d_in[6];
    const float* bn_beta      = (const float*)d_in[7];
    const float* res_w        = (const float*)d_in[8];
    const float* res_b        = (const float*)d_in[9];
    const float* res_bn_gamma = (const float*)d_in[10];
    const float* res_bn_beta  = (const float*)d_in[11];
    float* out = (float*)d_out;

    cudaFuncSetAttribute(res_gemm_tc, cudaFuncAttributeMaxDynamicSharedMemorySize,
                         RES_SMEM_BYTES);
    cudaFuncSetAttribute(main_gemm_tc, cudaFuncAttributeMaxDynamicSharedMemorySize,
                         MAIN_SMEM_BYTES);

    prep_kernel<<<25, 32>>>(hop, emb, A, b_block);
    cvt_resw_kernel<<<32, 256>>>(res_w);
    gbuild_kernel<<<dim3(33, 8), 256>>>(w_block);
    xprep_kernel<<<dim3(16, 8, 8), 256>>>(x);
    res_gemm_tc<<<dim3(25, 2, 16), 256, RES_SMEM_BYTES>>>(res_b);
    main_gemm_tc<<<dim3(16, 7, 8), 256, MAIN_SMEM_BYTES>>>();
    stats_kernel<<<512, 128>>>(bn_gamma, bn_beta, res_bn_gamma, res_bn_beta);
    final_kernel<<<4096, 256>>>(out);
}